// round 14
// baseline (speedup 1.0000x reference)
#include <cuda_runtime.h>
#include <cuda_bf16.h>
#include <math.h>
#include <stdint.h>

#define Bz 4
#define Sz 4096
#define Ez 512
#define Hz 8
#define Dz 64
#define Mz 2048
#define Lz 6
#define Nrows (Bz*Sz)
#define LN_EPS 1e-6f
#define KEPS 1e-3f
#define KVSZ (Bz*Hz*Dz*Dz)
#define ZSZ  (Bz*Hz*Dz)

// ---------------- device scratch ----------------
__device__ float g_x[Nrows*Ez];
__device__ float g_phiq[Nrows*Ez];
__device__ float g_phik[Nrows*Ez];
__device__ float g_v[Nrows*Ez];
__device__ float g_kv[Lz*KVSZ];
__device__ float g_z[Lz*ZSZ];
__device__ __align__(16) uint32_t g_hAhi[Nrows*256];
__device__ __align__(16) uint32_t g_hAlo[Nrows*256];
__device__ __align__(16) uint32_t g_ndhi[Nrows*256];
__device__ __align__(16) uint32_t g_ndlo[Nrows*256];
__device__ __align__(16) uint32_t g_pthi[Nrows*1024];
__device__ __align__(16) uint32_t g_ptlo[Nrows*1024];
#define OFQ 0
#define OO  2359296
#define O1  3145728
#define O2  6291456
#define WTOT 9437184
__device__ __align__(16) uint32_t g_whi[WTOT];
__device__ __align__(16) uint32_t g_wlo[WTOT];

// ---------------- helpers ----------------
__device__ __forceinline__ void split_pack(float x0, float x1,
                                           uint32_t& hi, uint32_t& lo) {
    __nv_bfloat162 h = __floats2bfloat162_rn(x0, x1);
    float r0 = x0 - __bfloat162float(h.x);
    float r1 = x1 - __bfloat162float(h.y);
    __nv_bfloat162 l = __floats2bfloat162_rn(r0, r1);
    hi = *reinterpret_cast<uint32_t*>(&h);
    lo = *reinterpret_cast<uint32_t*>(&l);
}
__device__ __forceinline__ void mma_bf16(float* c, uint4 a, uint2 b) {
    asm volatile(
        "mma.sync.aligned.m16n8k16.row.col.f32.bf16.bf16.f32 "
        "{%0,%1,%2,%3}, {%4,%5,%6,%7}, {%8,%9}, {%0,%1,%2,%3};"
        : "+f"(c[0]), "+f"(c[1]), "+f"(c[2]), "+f"(c[3])
        : "r"(a.x), "r"(a.y), "r"(a.z), "r"(a.w), "r"(b.x), "r"(b.y));
}
__device__ __forceinline__ float warp_sum(float v) {
    #pragma unroll
    for (int o = 16; o; o >>= 1) v += __shfl_xor_sync(0xffffffffu, v, o);
    return v;
}
__device__ __forceinline__ float gelu_tanh(float x) {
    float x3 = x * x * x;
    return 0.5f * x * (1.f + tanhf(0.7978845608028654f * (x + 0.044715f * x3)));
}
__device__ __forceinline__ void cp16(uint32_t dst, const void* src) {
    asm volatile("cp.async.cg.shared.global [%0], [%1], 16;\n" :: "r"(dst), "l"(src));
}
__device__ __forceinline__ void cp_commit() { asm volatile("cp.async.commit_group;\n"); }
template<int N>
__device__ __forceinline__ void cp_wait() {
    asm volatile("cp.async.wait_group %0;\n" :: "n"(N));
}

// ---------------- fused qkv weight split ----------------
__global__ void split_qkv(const float* __restrict__ wq, const float* __restrict__ wk,
                          const float* __restrict__ wv,
                          uint32_t* __restrict__ hi, uint32_t* __restrict__ lo) {
    int z = blockIdx.z, l = z / 3, m = z % 3;
    const float* Wl = (m == 0 ? wq : m == 1 ? wk : wv) + (size_t)l * Ez * Ez;
    uint32_t* hiL = hi + (size_t)l * 393216 + (size_t)m * 131072;
    uint32_t* loL = lo + (size_t)l * 393216 + (size_t)m * 131072;
    int c = blockIdx.x * 256 + threadIdx.x;
    int kb = blockIdx.y;
    int cb = c >> 7, nb = (c >> 3) & 15, g = c & 7;
    int stage = kb >> 1, kbS = kb & 1;
    uint32_t h8[8], l8[8];
    #pragma unroll
    for (int o = 0; o < 8; o++) {
        int tq = o >> 1, hb = o & 1;
        int k = kb * 16 + 2 * tq + 8 * hb;
        split_pack(Wl[(size_t)k * Ez + c], Wl[(size_t)(k + 1) * Ez + c], h8[o], l8[o]);
    }
    size_t I = ((size_t)(cb * 16 + stage)) * 2048 + (kbS * 16 + nb) * 64 + g * 8;
    *(uint4*)&hiL[I]     = *(uint4*)&h8[0];
    *(uint4*)&hiL[I + 4] = *(uint4*)&h8[4];
    *(uint4*)&loL[I]     = *(uint4*)&l8[0];
    *(uint4*)&loL[I + 4] = *(uint4*)&l8[4];
}

// ---------------- generic weight split ----------------
__global__ void split_w(const float* __restrict__ W,
                        uint32_t* __restrict__ hi, uint32_t* __restrict__ lo,
                        int K, int NC, size_t wStrideL, size_t oStrideL) {
    int l = blockIdx.z;
    const float* Wl = W + (size_t)l * wStrideL;
    uint32_t* hiL = hi + (size_t)l * oStrideL;
    uint32_t* loL = lo + (size_t)l * oStrideL;
    int c = blockIdx.x * 256 + threadIdx.x;
    int kb = blockIdx.y;
    int cb = c >> 7, nb = (c >> 3) & 15, g = c & 7;
    int stage = kb >> 1, kbS = kb & 1;
    uint32_t h8[8], l8[8];
    #pragma unroll
    for (int o = 0; o < 8; o++) {
        int tq = o >> 1, hb = o & 1;
        int k = kb * 16 + 2 * tq + 8 * hb;
        split_pack(Wl[(size_t)k * NC + c], Wl[(size_t)(k + 1) * NC + c], h8[o], l8[o]);
    }
    size_t I = ((size_t)(cb * (K >> 5) + stage)) * 2048 + (kbS * 16 + nb) * 64 + g * 8;
    *(uint4*)&hiL[I]     = *(uint4*)&h8[0];
    *(uint4*)&hiL[I + 4] = *(uint4*)&h8[4];
    *(uint4*)&loL[I]     = *(uint4*)&l8[0];
    *(uint4*)&loL[I + 4] = *(uint4*)&l8[4];
}

// ---------------- embedding + PE ----------------
__global__ void embed_pe_kernel(const int* __restrict__ inp,
                                const float* __restrict__ emb,
                                float* __restrict__ x) {
    int idx = blockIdx.x * blockDim.x + threadIdx.x;
    if (idx >= Nrows * Ez) return;
    int e = idx & (Ez - 1);
    int n = idx >> 9;
    int s = n & (Sz - 1);
    int tok = inp[n];
    int j = (e >> 1) * 2;
    const float c = -9.210340371976184f / (float)Ez;
    float ang = (float)s * expf((float)j * c);
    float pe = (e & 1) ? cosf(ang) : sinf(ang);
    x[idx] = emb[(size_t)tok * Ez + e] + pe;
}

// ---------------- zero all kv/z slices ----------------
__global__ void zero_all_kernel(float* kv, float* z) {
    int i = blockIdx.x * blockDim.x + threadIdx.x;
    if (i < Lz * KVSZ) kv[i] = 0.f;
    if (i < Lz * ZSZ) z[i] = 0.f;
}

// ---------------- final plain layernorm ----------------
__device__ __forceinline__ float block_sum(float val, float* red) {
    __syncthreads();
    int t = threadIdx.x;
    #pragma unroll
    for (int o = 16; o; o >>= 1) val += __shfl_down_sync(0xffffffffu, val, o);
    if ((t & 31) == 0) red[t >> 5] = val;
    __syncthreads();
    if (t < 32) {
        float r = (t < 8) ? red[t] : 0.f;
        #pragma unroll
        for (int o = 4; o; o >>= 1) r += __shfl_down_sync(0xffffffffu, r, o);
        if (t == 0) red[0] = r;
    }
    __syncthreads();
    return red[0];
}
__global__ void layernorm_kernel(const float* __restrict__ in,
                                 float* __restrict__ out,
                                 const float* __restrict__ scale,
                                 const float* __restrict__ bias) {
    __shared__ float red[32];
    int n = blockIdx.x;
    int t = threadIdx.x;
    const float* row = in + (size_t)n * Ez;
    float2 v = *(const float2*)&row[t * 2];
    float mu = block_sum(v.x + v.y, red) * (1.f / Ez);
    float dx = v.x - mu, dy = v.y - mu;
    float var = block_sum(dx * dx + dy * dy, red) * (1.f / Ez);
    float rs = rsqrtf(var + LN_EPS);
    float2 o;
    o.x = dx * rs * scale[t * 2 + 0] + bias[t * 2 + 0];
    o.y = dy * rs * scale[t * 2 + 1] + bias[t * 2 + 1];
    *(float2*)&out[(size_t)n * Ez + t * 2] = o;
}

// ---------------- layernorm -> split-permuted (16 rows/block) ----------------
__global__ void layernorm_split(const float* __restrict__ in,
                                uint32_t* __restrict__ outHi,
                                uint32_t* __restrict__ outLo,
                                const float* __restrict__ scale,
                                const float* __restrict__ bias) {
    __shared__ float nrm[16][516];
    int tid = threadIdx.x;
    int warp = tid >> 5, lane = tid & 31;
    long n0 = (long)blockIdx.x * 16;
    #pragma unroll
    for (int rr = 0; rr < 2; rr++) {
        int r = warp * 2 + rr;
        const float* row = in + (n0 + r) * Ez;
        float4 v[4];
        float s = 0.f;
        #pragma unroll
        for (int q = 0; q < 4; q++) {
            v[q] = *(const float4*)&row[lane * 4 + q * 128];
            s += v[q].x + v[q].y + v[q].z + v[q].w;
        }
        float mu = warp_sum(s) * (1.f / Ez);
        float vr = 0.f;
        #pragma unroll
        for (int q = 0; q < 4; q++) {
            float a = v[q].x - mu, b = v[q].y - mu, c = v[q].z - mu, d = v[q].w - mu;
            vr += a * a + b * b + c * c + d * d;
        }
        float rs = rsqrtf(warp_sum(vr) * (1.f / Ez) + LN_EPS);
        #pragma unroll
        for (int q = 0; q < 4; q++) {
            int c = lane * 4 + q * 128;
            float4 sc = *(const float4*)&scale[c];
            float4 bi = *(const float4*)&bias[c];
            float4 o;
            o.x = (v[q].x - mu) * rs * sc.x + bi.x;
            o.y = (v[q].y - mu) * rs * sc.y + bi.y;
            o.z = (v[q].z - mu) * rs * sc.z + bi.z;
            o.w = (v[q].w - mu) * rs * sc.w + bi.w;
            *(float4*)&nrm[r][c] = o;
        }
    }
    __syncthreads();
    int g = tid & 7, kb = (tid >> 3) & 1, stage = tid >> 4;
    uint32_t hi[16], lo[16];
    #pragma unroll
    for (int o = 0; o < 16; o++) {
        int tq = o >> 2, kbit = (o >> 1) & 1, rbit = o & 1;
        int c = stage * 32 + kb * 16 + 2 * tq + 8 * kbit;
        int rl = g + 8 * rbit;
        split_pack(nrm[rl][c], nrm[rl][c + 1], hi[o], lo[o]);
    }
    size_t I = ((size_t)((blockIdx.x >> 3) * 16 + stage)) * 2048
             + ((blockIdx.x & 7) * 2 + kb) * 128 + g * 16;
    *(uint4*)&outHi[I]      = *(uint4*)&hi[0];
    *(uint4*)&outHi[I + 4]  = *(uint4*)&hi[4];
    *(uint4*)&outHi[I + 8]  = *(uint4*)&hi[8];
    *(uint4*)&outHi[I + 12] = *(uint4*)&hi[12];
    *(uint4*)&outLo[I]      = *(uint4*)&lo[0];
    *(uint4*)&outLo[I + 4]  = *(uint4*)&lo[4];
    *(uint4*)&outLo[I + 8]  = *(uint4*)&lo[8];
    *(uint4*)&outLo[I + 12] = *(uint4*)&lo[12];
}

// ---------------- tensor-core GEMM (R8 config: 256 thr, 3-stage, 2 CTA/SM) --
#define SMEM_BYTES 98304
template<int EPI, int OUT>
__global__ void __launch_bounds__(256, 2)
gemm_tc(const uint32_t* __restrict__ Ahi, const uint32_t* __restrict__ Alo,
        const uint32_t* __restrict__ Bhi, const uint32_t* __restrict__ Blo,
        float* __restrict__ C, int K, int NC,
        const float* __restrict__ bias, const float* __restrict__ resid,
        const int* __restrict__ maskTok,
        uint32_t* __restrict__ outHi, uint32_t* __restrict__ outLo,
        float* __restrict__ oq, float* __restrict__ ok, float* __restrict__ ov) {
    extern __shared__ uint32_t sm[];
    const int tid = threadIdx.x;
    const int lane = tid & 31, warp = tid >> 5;
    const int wm = warp & 1, wn = warp >> 1;
    const int g = lane >> 2, tq = lane & 3;
    const int NS = K >> 5;
    const size_t aBase = (size_t)blockIdx.y * NS * 2048;
    const size_t bBase = (size_t)blockIdx.x * NS * 2048;
    const uint32_t smBase = (uint32_t)__cvta_generic_to_shared(sm);

    float acc[4][4][4];
    #pragma unroll
    for (int mt = 0; mt < 4; mt++)
        #pragma unroll
        for (int nt = 0; nt < 4; nt++)
            #pragma unroll
            for (int r = 0; r < 4; r++) acc[mt][nt][r] = 0.f;

    auto issue = [&](int s) {
        uint32_t d = smBase + (s % 3) * 32768 + tid * 16;
        const uint32_t* a1 = Ahi + aBase + (size_t)s * 2048 + tid * 4;
        const uint32_t* a2 = Alo + aBase + (size_t)s * 2048 + tid * 4;
        const uint32_t* b1 = Bhi + bBase + (size_t)s * 2048 + tid * 4;
        const uint32_t* b2 = Blo + bBase + (size_t)s * 2048 + tid * 4;
        cp16(d,          a1); cp16(d + 4096,  a1 + 1024);
        cp16(d + 8192,   a2); cp16(d + 12288, a2 + 1024);
        cp16(d + 16384,  b1); cp16(d + 20480, b1 + 1024);
        cp16(d + 24576,  b2); cp16(d + 28672, b2 + 1024);
    };

    issue(0); cp_commit();
    issue(1); cp_commit();

    for (int s = 0; s < NS; s++) {
        if (s + 1 < NS) cp_wait<1>(); else cp_wait<0>();
        __syncthreads();
        if (s + 2 < NS) { issue(s + 2); cp_commit(); }
        int base = (s % 3) * 8192;
        #pragma unroll
        for (int kb = 0; kb < 2; kb++) {
            uint4 Ah[4], Al[4]; uint2 Bh[4], Bl[4];
            #pragma unroll
            for (int mt = 0; mt < 4; mt++) {
                int blk = base + ((wm * 4 + mt) * 2 + kb) * 128 + lane * 4;
                Ah[mt] = *(uint4*)&sm[blk];
                Al[mt] = *(uint4*)&sm[blk + 2048];
            }
            #pragma unroll
            for (int nt = 0; nt < 4; nt++) {
                int bo = base + 4096 + (kb * 16 + wn * 4 + nt) * 64 + lane * 2;
                Bh[nt] = *(uint2*)&sm[bo];
                Bl[nt] = *(uint2*)&sm[bo + 2048];
            }
            #pragma unroll
            for (int mt = 0; mt < 4; mt++)
                #pragma unroll
                for (int nt = 0; nt < 4; nt++)
                    mma_bf16(acc[mt][nt], Ah[mt], Bh[nt]);
            #pragma unroll
            for (int mt = 0; mt < 4; mt++)
                #pragma unroll
                for (int nt = 0; nt < 4; nt++)
                    mma_bf16(acc[mt][nt], Ah[mt], Bl[nt]);
            #pragma unroll
            for (int mt = 0; mt < 4; mt++)
                #pragma unroll
                for (int nt = 0; nt < 4; nt++)
                    mma_bf16(acc[mt][nt], Al[mt], Bh[nt]);
        }
    }

    const long rowBase = (long)blockIdx.y * 128;
    const int colBase = blockIdx.x * 128;

    if (OUT == 1) {
        #pragma unroll
        for (int mt = 0; mt < 4; mt++) {
            float tv[4][4];
            #pragma unroll
            for (int nt = 0; nt < 4; nt++) {
                int c = colBase + wn * 32 + nt * 8 + 2 * tq;
                float b0 = bias[c], b1 = bias[c + 1];
                tv[nt][0] = gelu_tanh(acc[mt][nt][0] + b0);
                tv[nt][1] = gelu_tanh(acc[mt][nt][1] + b1);
                tv[nt][2] = gelu_tanh(acc[mt][nt][2] + b0);
                tv[nt][3] = gelu_tanh(acc[mt][nt][3] + b1);
            }
            #pragma unroll
            for (int ntp = 0; ntp < 2; ntp++) {
                uint4 hv, lv;
                split_pack(tv[2*ntp][0],   tv[2*ntp][1],   hv.x, lv.x);
                split_pack(tv[2*ntp][2],   tv[2*ntp][3],   hv.y, lv.y);
                split_pack(tv[2*ntp+1][0], tv[2*ntp+1][1], hv.z, lv.z);
                split_pack(tv[2*ntp+1][2], tv[2*ntp+1][3], hv.w, lv.w);
                size_t I = ((size_t)blockIdx.y * (NC >> 5) + blockIdx.x * 4 + wn) * 2048
                         + ((wm * 4 + mt) * 2 + ntp) * 128 + g * 16 + tq * 4;
                *(uint4*)&outHi[I] = hv;
                *(uint4*)&outLo[I] = lv;
            }
        }
        return;
    }

    if (EPI == 6) {
        int mat = colBase >> 9;
        int cc0 = colBase & 511;
        float* dst = (mat == 0) ? oq : (mat == 1) ? ok : ov;
        #pragma unroll
        for (int mt = 0; mt < 4; mt++) {
            long r0 = rowBase + wm * 64 + mt * 16 + g;
            long r1 = r0 + 8;
            float m0 = 1.f, m1 = 1.f;
            if (mat == 1) {
                m0 = (maskTok[r0] > 0) ? 1.f : 0.f;
                m1 = (maskTok[r1] > 0) ? 1.f : 0.f;
            }
            #pragma unroll
            for (int nt = 0; nt < 4; nt++) {
                int c = cc0 + wn * 32 + nt * 8 + 2 * tq;
                float v0 = acc[mt][nt][0], v1 = acc[mt][nt][1];
                float v2 = acc[mt][nt][2], v3 = acc[mt][nt][3];
                if (mat == 0) {
                    v0 = fmaxf(v0, 0.f) + KEPS; v1 = fmaxf(v1, 0.f) + KEPS;
                    v2 = fmaxf(v2, 0.f) + KEPS; v3 = fmaxf(v3, 0.f) + KEPS;
                } else if (mat == 1) {
                    v0 = (fmaxf(v0, 0.f) + KEPS) * m0; v1 = (fmaxf(v1, 0.f) + KEPS) * m0;
                    v2 = (fmaxf(v2, 0.f) + KEPS) * m1; v3 = (fmaxf(v3, 0.f) + KEPS) * m1;
                }
                float2 o0 = {v0, v1}, o1 = {v2, v3};
                *(float2*)&dst[(size_t)r0 * 512 + c] = o0;
                *(float2*)&dst[(size_t)r1 * 512 + c] = o1;
            }
        }
        return;
    }

    #pragma unroll
    for (int mt = 0; mt < 4; mt++) {
        long r0 = rowBase + wm * 64 + mt * 16 + g;
        long r1 = r0 + 8;
        #pragma unroll
        for (int nt = 0; nt < 4; nt++) {
            int c = colBase + wn * 32 + nt * 8 + 2 * tq;
            float v0 = acc[mt][nt][0], v1 = acc[mt][nt][1];
            float v2 = acc[mt][nt][2], v3 = acc[mt][nt][3];
            if (EPI == 4) {
                float b0 = bias[c], b1 = bias[c + 1];
                v0 += b0; v1 += b1; v2 += b0; v3 += b1;
            }
            v0 += resid[(size_t)r0 * NC + c];
            v1 += resid[(size_t)r0 * NC + c + 1];
            v2 += resid[(size_t)r1 * NC + c];
            v3 += resid[(size_t)r1 * NC + c + 1];
            float2 o0 = {v0, v1}, o1 = {v2, v3};
            *(float2*)&C[(size_t)r0 * NC + c] = o0;
            *(float2*)&C[(size_t)r1 * NC + c] = o1;
        }
    }
}

// ---------------- kv = phik^T @ v, z = sum phik ----------------
#define KV_SPLITS 32
__global__ void kv_kernel(const float* __restrict__ phik,
                          const float* __restrict__ v,
                          float* __restrict__ kv, float* __restrict__ z) {
    int bh = blockIdx.x, split = blockIdx.y;
    int b = bh >> 3, h = bh & 7;
    const int CH = Sz / KV_SPLITS;
    int s0 = split * CH;
    __shared__ float ks[32][64];
    __shared__ float vs[32][64];
    int tid = threadIdx.x;
    int tx = tid & 15, ty = tid >> 4;
    float acc[4][4];
    #pragma unroll
    for (int i = 0; i < 4; i++)
        #pragma unroll
        for (int j = 0; j < 4; j++) acc[i][j] = 0.f;
    float zacc[4] = {0.f, 0.f, 0.f, 0.f};
    for (int c = 0; c < CH; c += 32) {
        #pragma unroll
        for (int r = 0; r < 2; r++) {
            int f4 = tid + r * 256;
            int row = f4 >> 4, col = (f4 & 15) * 4;
            size_t base = ((size_t)(b * Sz + s0 + c + row)) * Ez + h * 64 + col;
            *(float4*)&ks[row][col] = *(const float4*)&phik[base];
            *(float4*)&vs[row][col] = *(const float4*)&v[base];
        }
        __syncthreads();
        #pragma unroll
        for (int s = 0; s < 32; s++) {
            float a[4], bb[4];
            #pragma unroll
            for (int i = 0; i < 4; i++) { a[i] = ks[s][ty * 4 + i]; bb[i] = vs[s][tx * 4 + i]; }
            #pragma unroll
            for (int i = 0; i < 4; i++)
                #pragma unroll
                for (int j = 0; j < 4; j++) acc[i][j] = fmaf(a[i], bb[j], acc[i][j]);
            if (tx == 0)
                #pragma unroll
                for (int i = 0; i < 4; i++) zacc[i] += a[i];
        }
        __syncthreads();
    }
    float* kvp = kv + bh * Dz * Dz;
    #pragma unroll
    for (int i = 0; i < 4; i++)
        #pragma unroll
        for (int j = 0; j < 4; j++)
            atomicAdd(&kvp[(ty * 4 + i) * 64 + tx * 4 + j], acc[i][j]);
    if (tx == 0)
        #pragma unroll
        for (int i = 0; i < 4; i++)
            atomicAdd(&z[bh * 64 + ty * 4 + i], zacc[i]);
}

// ---------------- numden v2: register-blocked, 1 row x 16 cols per thread --
__global__ void numden_split(const float* __restrict__ phiq,
                             const float* __restrict__ kv,
                             const float* __restrict__ z,
                             uint32_t* __restrict__ outHi,
                             uint32_t* __restrict__ outLo) {
    int bh = blockIdx.x, chunk = blockIdx.y;
    int b = bh >> 3, h = bh & 7;
    __shared__ float kvs[64][68];
    __shared__ float zs[64];
    __shared__ float buf[64][68];
    int tid = threadIdx.x;
    int s0 = chunk * 64;

    for (int idx = tid; idx < 4096; idx += 256)
        kvs[idx >> 6][idx & 63] = kv[bh * Dz * Dz + idx];
    if (tid < 64) zs[tid] = z[bh * 64 + tid];
    {
        int r = tid >> 2, c4 = (tid & 3) * 16;
        size_t base = ((size_t)(b * Sz + s0 + r)) * Ez + h * 64 + c4;
        #pragma unroll
        for (int q = 0; q < 4; q++)
            *(float4*)&buf[r][c4 + q * 4] = *(const float4*)&phiq[base + q * 4];
    }
    __syncthreads();

    const int row = tid >> 2, cg = (tid & 3) * 16;
    float acc[16];
    #pragma unroll
    for (int j = 0; j < 16; j++) acc[j] = 0.f;
    float den = 0.f;
    for (int m = 0; m < 64; m++) {
        float p = buf[row][m];
        den = fmaf(p, zs[m], den);
        #pragma unroll
        for (int q = 0; q < 4; q++) {
            float4 k4 = *(const float4*)&kvs[m][cg + q * 4];
            acc[q * 4 + 0] = fmaf(p, k4.x, acc[q * 4 + 0]);
            acc[q * 4 + 1] = fmaf(p, k4.y, acc[q * 4 + 1]);
            acc[q * 4 + 2] = fmaf(p, k4.z, acc[q * 4 + 2]);
            acc[q * 4 + 3] = fmaf(p, k4.w, acc[q * 4 + 3]);
        }
    }
    __syncthreads();
    float inv = 1.f / den;
    #pragma unroll
    for (int q = 0; q < 4; q++) {
        float4 o;
        o.x = acc[q * 4 + 0] * inv; o.y = acc[q * 4 + 1] * inv;
        o.z = acc[q * 4 + 2] * inv; o.w = acc[q * 4 + 3] * inv;
        *(float4*)&buf[row][cg + q * 4] = o;
    }
    __syncthreads();

    int g = tid & 7, halfRun = (tid >> 3) & 1, kb = (tid >> 4) & 1;
    int s2 = (tid >> 5) & 1, mtl = tid >> 6;
    long rowTile = ((long)b * Sz + chunk * 64) >> 7;
    int mtG = (chunk & 1) * 4 + mtl;
    int stage = h * 2 + s2;
    uint32_t hi[8], lo[8];
    #pragma unroll
    for (int o = 0; o < 8; o++) {
        int tqv = halfRun * 2 + (o >> 2);
        int kbit = (o >> 1) & 1, rbit = o & 1;
        int rl = mtl * 16 + g + 8 * rbit;
        int cl = s2 * 32 + kb * 16 + 2 * tqv + 8 * kbit;
        split_pack(buf[rl][cl], buf[rl][cl + 1], hi[o], lo[o]);
    }
    size_t I = ((size_t)(rowTile * 16 + stage)) * 2048
             + (mtG * 2 + kb) * 128 + g * 16 + halfRun * 8;
    *(uint4*)&outHi[I]     = *(uint4*)&hi[0];
    *(uint4*)&outHi[I + 4] = *(uint4*)&hi[4];
    *(uint4*)&outLo[I]     = *(uint4*)&lo[0];
    *(uint4*)&outLo[I + 4] = *(uint4*)&lo[4];
}

// ---------------- host ----------------
extern "C" void kernel_launch(void* const* d_in, const int* in_sizes, int n_in,
                              void* d_out, int out_size) {
    const int*   inputs    = (const int*)  d_in[0];
    const float* embed     = (const float*)d_in[1];
    const float* ln1_scale = (const float*)d_in[2];
    const float* ln1_bias  = (const float*)d_in[3];
    const float* wq        = (const float*)d_in[4];
    const float* wk        = (const float*)d_in[5];
    const float* wv        = (const float*)d_in[6];
    const float* wo        = (const float*)d_in[7];
    const float* ln2_scale = (const float*)d_in[8];
    const float* ln2_bias  = (const float*)d_in[9];
    const float* w1        = (const float*)d_in[10];
    const float* b1        = (const float*)d_in[11];
    const float* w2        = (const float*)d_in[12];
    const float* b2        = (const float*)d_in[13];
    const float* lnf_scale = (const float*)d_in[14];
    const float* lnf_bias  = (const float*)d_in[15];
    float* out = (float*)d_out;

    static float *px = nullptr, *pq, *pk, *pv, *pkv, *pz;
    static uint32_t *hAhi, *hAlo, *ndhi, *ndlo, *pthi, *ptlo, *whi, *wlo;
    if (!px) {
        cudaGetSymbolAddress((void**)&px,   g_x);
        cudaGetSymbolAddress((void**)&pq,   g_phiq);
        cudaGetSymbolAddress((void**)&pk,   g_phik);
        cudaGetSymbolAddress((void**)&pv,   g_v);
        cudaGetSymbolAddress((void**)&pkv,  g_kv);
        cudaGetSymbolAddress((void**)&pz,   g_z);
        cudaGetSymbolAddress((void**)&hAhi, g_hAhi);
        cudaGetSymbolAddress((void**)&hAlo, g_hAlo);
        cudaGetSymbolAddress((void**)&ndhi, g_ndhi);
        cudaGetSymbolAddress((void**)&ndlo, g_ndlo);
        cudaGetSymbolAddress((void**)&pthi, g_pthi);
        cudaGetSymbolAddress((void**)&ptlo, g_ptlo);
        cudaGetSymbolAddress((void**)&whi,  g_whi);
        cudaGetSymbolAddress((void**)&wlo,  g_wlo);
        cudaFuncSetAttribute(gemm_tc<6,0>, cudaFuncAttributeMaxDynamicSharedMemorySize, SMEM_BYTES);
        cudaFuncSetAttribute(gemm_tc<5,0>, cudaFuncAttributeMaxDynamicSharedMemorySize, SMEM_BYTES);
        cudaFuncSetAttribute(gemm_tc<3,1>, cudaFuncAttributeMaxDynamicSharedMemorySize, SMEM_BYTES);
        cudaFuncSetAttribute(gemm_tc<4,0>, cudaFuncAttributeMaxDynamicSharedMemorySize, SMEM_BYTES);
    }

    dim3 gQKV(12, Nrows / 128);
    dim3 gE(4, Nrows / 128);
    dim3 gM(16, Nrows / 128);
    dim3 gKV(Bz * Hz, KV_SPLITS);
    dim3 gND(Bz * Hz, Sz / 64);

    // our launches: 0 split_qkv, 1 embed, 2 ln1(l0), 3 PROBE numden (ncu -s 5),
    // 4 zero_all, 5 qkv(l0), ... Probe output (ndhi/ndlo) is fully overwritten
    // by layer 0's real numden before any consumer reads it.
    split_qkv<<<dim3(2, 32, 3 * Lz), 256>>>(wq, wk, wv, whi + OFQ, wlo + OFQ);
    embed_pe_kernel<<<(Nrows * Ez + 255) / 256, 256>>>(inputs, embed, px);
    layernorm_split<<<Nrows / 16, 256>>>(px, hAhi, hAlo, ln1_scale, ln1_bias);
    numden_split<<<gND, 256>>>(pq, pkv, pz, ndhi, ndlo);   // PROBE
    zero_all_kernel<<<(Lz * KVSZ + 255) / 256, 256>>>(pkv, pz);
    gemm_tc<6,0><<<gQKV, 256, SMEM_BYTES>>>(hAhi, hAlo, whi + OFQ, wlo + OFQ,
                                            nullptr, Ez, 512, nullptr, nullptr, inputs,
                                            nullptr, nullptr, pq, pk, pv);
    split_w<<<dim3(2, 32, Lz), 256>>>(wo, whi + OO, wlo + OO, Ez, Ez, (size_t)Ez*Ez, 131072);
    split_w<<<dim3(8, 32, Lz), 256>>>(w1, whi + O1, wlo + O1, Ez, Mz, (size_t)Ez*Mz, 524288);
    split_w<<<dim3(2, 128, Lz), 256>>>(w2, whi + O2, wlo + O2, Mz, Ez, (size_t)Mz*Ez, 524288);

    for (int l = 0; l < Lz; l++) {
        const uint32_t* fqh = whi + OFQ + (size_t)l * 393216;
        const uint32_t* fql = wlo + OFQ + (size_t)l * 393216;
        const uint32_t* woh = whi + OO + (size_t)l * 131072;
        const uint32_t* wol = wlo + OO + (size_t)l * 131072;
        const uint32_t* w1h = whi + O1 + (size_t)l * 524288;
        const uint32_t* w1l = wlo + O1 + (size_t)l * 524288;
        const uint32_t* w2h = whi + O2 + (size_t)l * 524288;
        const uint32_t* w2l = wlo + O2 + (size_t)l * 524288;
        float* kvL = pkv + (size_t)l * KVSZ;
        float* zL  = pz  + (size_t)l * ZSZ;

        if (l > 0) {
            layernorm_split<<<Nrows / 16, 256>>>(px, hAhi, hAlo,
                                                 ln1_scale + l * Ez, ln1_bias + l * Ez);
            gemm_tc<6,0><<<gQKV, 256, SMEM_BYTES>>>(hAhi, hAlo, fqh, fql,
                                                    nullptr, Ez, 512, nullptr, nullptr, inputs,
                                                    nullptr, nullptr, pq, pk, pv);
        }
        kv_kernel<<<gKV, 256>>>(pk, pv, kvL, zL);
        numden_split<<<gND, 256>>>(pq, kvL, zL, ndhi, ndlo);
        gemm_tc<5,0><<<gE, 256, SMEM_BYTES>>>(ndhi, ndlo, woh, wol, px, Ez, Ez,
                                              nullptr, px, nullptr, nullptr, nullptr,
                                              nullptr, nullptr, nullptr);
        layernorm_split<<<Nrows / 16, 256>>>(px, hAhi, hAlo,
                                             ln2_scale + l * Ez, ln2_bias + l * Ez);
        gemm_tc<3,1><<<gM, 256, SMEM_BYTES>>>(hAhi, hAlo, w1h, w1l, nullptr, Ez, Mz,
                                              b1 + (size_t)l * Mz, nullptr, nullptr,
                                              pthi, ptlo, nullptr, nullptr, nullptr);
        gemm_tc<4,0><<<gE, 256, SMEM_BYTES>>>(pthi, ptlo, w2h, w2l, px, Mz, Ez,
                                              b2 + (size_t)l * Ez, px, nullptr,
                                              nullptr, nullptr, nullptr, nullptr, nullptr);
    }

    layernorm_kernel<<<Nrows, 256>>>(px, out, lnf_scale, lnf_bias);
}

// round 15
// speedup vs baseline: 1.0245x; 1.0245x over previous
#include <cuda_runtime.h>
#include <cuda_bf16.h>
#include <math.h>
#include <stdint.h>

#define Bz 4
#define Sz 4096
#define Ez 512
#define Hz 8
#define Dz 64
#define Mz 2048
#define Lz 6
#define Nrows (Bz*Sz)
#define LN_EPS 1e-6f
#define KEPS 1e-3f
#define KVSZ (Bz*Hz*Dz*Dz)
#define ZSZ  (Bz*Hz*Dz)

// ---------------- device scratch ----------------
__device__ float g_x[Nrows*Ez];
__device__ float g_phiq[Nrows*Ez];
__device__ float g_phik[Nrows*Ez];
__device__ float g_v[Nrows*Ez];
__device__ float g_kv[Lz*KVSZ];
__device__ float g_z[Lz*ZSZ];
__device__ __align__(16) uint32_t g_hAhi[Nrows*256];
__device__ __align__(16) uint32_t g_hAlo[Nrows*256];
__device__ __align__(16) uint32_t g_ndhi[Nrows*256];
__device__ __align__(16) uint32_t g_ndlo[Nrows*256];
__device__ __align__(16) uint32_t g_pthi[Nrows*1024];
__device__ __align__(16) uint32_t g_ptlo[Nrows*1024];
#define OFQ 0
#define OO  2359296
#define O1  3145728
#define O2  6291456
#define WTOT 9437184
__device__ __align__(16) uint32_t g_whi[WTOT];
__device__ __align__(16) uint32_t g_wlo[WTOT];

// ---------------- helpers ----------------
__device__ __forceinline__ void split_pack(float x0, float x1,
                                           uint32_t& hi, uint32_t& lo) {
    __nv_bfloat162 h = __floats2bfloat162_rn(x0, x1);
    float r0 = x0 - __bfloat162float(h.x);
    float r1 = x1 - __bfloat162float(h.y);
    __nv_bfloat162 l = __floats2bfloat162_rn(r0, r1);
    hi = *reinterpret_cast<uint32_t*>(&h);
    lo = *reinterpret_cast<uint32_t*>(&l);
}
__device__ __forceinline__ void mma_bf16(float* c, uint4 a, uint2 b) {
    asm volatile(
        "mma.sync.aligned.m16n8k16.row.col.f32.bf16.bf16.f32 "
        "{%0,%1,%2,%3}, {%4,%5,%6,%7}, {%8,%9}, {%0,%1,%2,%3};"
        : "+f"(c[0]), "+f"(c[1]), "+f"(c[2]), "+f"(c[3])
        : "r"(a.x), "r"(a.y), "r"(a.z), "r"(a.w), "r"(b.x), "r"(b.y));
}
__device__ __forceinline__ float warp_sum(float v) {
    #pragma unroll
    for (int o = 16; o; o >>= 1) v += __shfl_xor_sync(0xffffffffu, v, o);
    return v;
}
__device__ __forceinline__ float gelu_tanh(float x) {
    float x3 = x * x * x;
    return 0.5f * x * (1.f + tanhf(0.7978845608028654f * (x + 0.044715f * x3)));
}
__device__ __forceinline__ void cp16(uint32_t dst, const void* src) {
    asm volatile("cp.async.cg.shared.global [%0], [%1], 16;\n" :: "r"(dst), "l"(src));
}
__device__ __forceinline__ void cp_commit() { asm volatile("cp.async.commit_group;\n"); }
template<int N>
__device__ __forceinline__ void cp_wait() {
    asm volatile("cp.async.wait_group %0;\n" :: "n"(N));
}

// ---------------- fused qkv weight split ----------------
__global__ void split_qkv(const float* __restrict__ wq, const float* __restrict__ wk,
                          const float* __restrict__ wv,
                          uint32_t* __restrict__ hi, uint32_t* __restrict__ lo) {
    int z = blockIdx.z, l = z / 3, m = z % 3;
    const float* Wl = (m == 0 ? wq : m == 1 ? wk : wv) + (size_t)l * Ez * Ez;
    uint32_t* hiL = hi + (size_t)l * 393216 + (size_t)m * 131072;
    uint32_t* loL = lo + (size_t)l * 393216 + (size_t)m * 131072;
    int c = blockIdx.x * 256 + threadIdx.x;
    int kb = blockIdx.y;
    int cb = c >> 7, nb = (c >> 3) & 15, g = c & 7;
    int stage = kb >> 1, kbS = kb & 1;
    uint32_t h8[8], l8[8];
    #pragma unroll
    for (int o = 0; o < 8; o++) {
        int tq = o >> 1, hb = o & 1;
        int k = kb * 16 + 2 * tq + 8 * hb;
        split_pack(Wl[(size_t)k * Ez + c], Wl[(size_t)(k + 1) * Ez + c], h8[o], l8[o]);
    }
    size_t I = ((size_t)(cb * 16 + stage)) * 2048 + (kbS * 16 + nb) * 64 + g * 8;
    *(uint4*)&hiL[I]     = *(uint4*)&h8[0];
    *(uint4*)&hiL[I + 4] = *(uint4*)&h8[4];
    *(uint4*)&loL[I]     = *(uint4*)&l8[0];
    *(uint4*)&loL[I + 4] = *(uint4*)&l8[4];
}

// ---------------- generic weight split ----------------
__global__ void split_w(const float* __restrict__ W,
                        uint32_t* __restrict__ hi, uint32_t* __restrict__ lo,
                        int K, int NC, size_t wStrideL, size_t oStrideL) {
    int l = blockIdx.z;
    const float* Wl = W + (size_t)l * wStrideL;
    uint32_t* hiL = hi + (size_t)l * oStrideL;
    uint32_t* loL = lo + (size_t)l * oStrideL;
    int c = blockIdx.x * 256 + threadIdx.x;
    int kb = blockIdx.y;
    int cb = c >> 7, nb = (c >> 3) & 15, g = c & 7;
    int stage = kb >> 1, kbS = kb & 1;
    uint32_t h8[8], l8[8];
    #pragma unroll
    for (int o = 0; o < 8; o++) {
        int tq = o >> 1, hb = o & 1;
        int k = kb * 16 + 2 * tq + 8 * hb;
        split_pack(Wl[(size_t)k * NC + c], Wl[(size_t)(k + 1) * NC + c], h8[o], l8[o]);
    }
    size_t I = ((size_t)(cb * (K >> 5) + stage)) * 2048 + (kbS * 16 + nb) * 64 + g * 8;
    *(uint4*)&hiL[I]     = *(uint4*)&h8[0];
    *(uint4*)&hiL[I + 4] = *(uint4*)&h8[4];
    *(uint4*)&loL[I]     = *(uint4*)&l8[0];
    *(uint4*)&loL[I + 4] = *(uint4*)&l8[4];
}

// ---------------- embedding + PE ----------------
__global__ void embed_pe_kernel(const int* __restrict__ inp,
                                const float* __restrict__ emb,
                                float* __restrict__ x) {
    int idx = blockIdx.x * blockDim.x + threadIdx.x;
    if (idx >= Nrows * Ez) return;
    int e = idx & (Ez - 1);
    int n = idx >> 9;
    int s = n & (Sz - 1);
    int tok = inp[n];
    int j = (e >> 1) * 2;
    const float c = -9.210340371976184f / (float)Ez;
    float ang = (float)s * expf((float)j * c);
    float pe = (e & 1) ? cosf(ang) : sinf(ang);
    x[idx] = emb[(size_t)tok * Ez + e] + pe;
}

// ---------------- zero all kv/z slices ----------------
__global__ void zero_all_kernel(float* kv, float* z) {
    int i = blockIdx.x * blockDim.x + threadIdx.x;
    if (i < Lz * KVSZ) kv[i] = 0.f;
    if (i < Lz * ZSZ) z[i] = 0.f;
}

// ---------------- final plain layernorm ----------------
__device__ __forceinline__ float block_sum(float val, float* red) {
    __syncthreads();
    int t = threadIdx.x;
    #pragma unroll
    for (int o = 16; o; o >>= 1) val += __shfl_down_sync(0xffffffffu, val, o);
    if ((t & 31) == 0) red[t >> 5] = val;
    __syncthreads();
    if (t < 32) {
        float r = (t < 8) ? red[t] : 0.f;
        #pragma unroll
        for (int o = 4; o; o >>= 1) r += __shfl_down_sync(0xffffffffu, r, o);
        if (t == 0) red[0] = r;
    }
    __syncthreads();
    return red[0];
}
__global__ void layernorm_kernel(const float* __restrict__ in,
                                 float* __restrict__ out,
                                 const float* __restrict__ scale,
                                 const float* __restrict__ bias) {
    __shared__ float red[32];
    int n = blockIdx.x;
    int t = threadIdx.x;
    const float* row = in + (size_t)n * Ez;
    float2 v = *(const float2*)&row[t * 2];
    float mu = block_sum(v.x + v.y, red) * (1.f / Ez);
    float dx = v.x - mu, dy = v.y - mu;
    float var = block_sum(dx * dx + dy * dy, red) * (1.f / Ez);
    float rs = rsqrtf(var + LN_EPS);
    float2 o;
    o.x = dx * rs * scale[t * 2 + 0] + bias[t * 2 + 0];
    o.y = dy * rs * scale[t * 2 + 1] + bias[t * 2 + 1];
    *(float2*)&out[(size_t)n * Ez + t * 2] = o;
}

// ---------------- layernorm -> split-permuted (16 rows/block) ----------------
__global__ void layernorm_split(const float* __restrict__ in,
                                uint32_t* __restrict__ outHi,
                                uint32_t* __restrict__ outLo,
                                const float* __restrict__ scale,
                                const float* __restrict__ bias) {
    __shared__ float nrm[16][516];
    int tid = threadIdx.x;
    int warp = tid >> 5, lane = tid & 31;
    long n0 = (long)blockIdx.x * 16;
    #pragma unroll
    for (int rr = 0; rr < 2; rr++) {
        int r = warp * 2 + rr;
        const float* row = in + (n0 + r) * Ez;
        float4 v[4];
        float s = 0.f;
        #pragma unroll
        for (int q = 0; q < 4; q++) {
            v[q] = *(const float4*)&row[lane * 4 + q * 128];
            s += v[q].x + v[q].y + v[q].z + v[q].w;
        }
        float mu = warp_sum(s) * (1.f / Ez);
        float vr = 0.f;
        #pragma unroll
        for (int q = 0; q < 4; q++) {
            float a = v[q].x - mu, b = v[q].y - mu, c = v[q].z - mu, d = v[q].w - mu;
            vr += a * a + b * b + c * c + d * d;
        }
        float rs = rsqrtf(warp_sum(vr) * (1.f / Ez) + LN_EPS);
        #pragma unroll
        for (int q = 0; q < 4; q++) {
            int c = lane * 4 + q * 128;
            float4 sc = *(const float4*)&scale[c];
            float4 bi = *(const float4*)&bias[c];
            float4 o;
            o.x = (v[q].x - mu) * rs * sc.x + bi.x;
            o.y = (v[q].y - mu) * rs * sc.y + bi.y;
            o.z = (v[q].z - mu) * rs * sc.z + bi.z;
            o.w = (v[q].w - mu) * rs * sc.w + bi.w;
            *(float4*)&nrm[r][c] = o;
        }
    }
    __syncthreads();
    int g = tid & 7, kb = (tid >> 3) & 1, stage = tid >> 4;
    uint32_t hi[16], lo[16];
    #pragma unroll
    for (int o = 0; o < 16; o++) {
        int tq = o >> 2, kbit = (o >> 1) & 1, rbit = o & 1;
        int c = stage * 32 + kb * 16 + 2 * tq + 8 * kbit;
        int rl = g + 8 * rbit;
        split_pack(nrm[rl][c], nrm[rl][c + 1], hi[o], lo[o]);
    }
    size_t I = ((size_t)((blockIdx.x >> 3) * 16 + stage)) * 2048
             + ((blockIdx.x & 7) * 2 + kb) * 128 + g * 16;
    *(uint4*)&outHi[I]      = *(uint4*)&hi[0];
    *(uint4*)&outHi[I + 4]  = *(uint4*)&hi[4];
    *(uint4*)&outHi[I + 8]  = *(uint4*)&hi[8];
    *(uint4*)&outHi[I + 12] = *(uint4*)&hi[12];
    *(uint4*)&outLo[I]      = *(uint4*)&lo[0];
    *(uint4*)&outLo[I + 4]  = *(uint4*)&lo[4];
    *(uint4*)&outLo[I + 8]  = *(uint4*)&lo[8];
    *(uint4*)&outLo[I + 12] = *(uint4*)&lo[12];
}

// ---------------- tensor-core GEMM (R8 config: 256 thr, 3-stage, 2 CTA/SM) --
#define SMEM_BYTES 98304
template<int EPI, int OUT>
__global__ void __launch_bounds__(256, 2)
gemm_tc(const uint32_t* __restrict__ Ahi, const uint32_t* __restrict__ Alo,
        const uint32_t* __restrict__ Bhi, const uint32_t* __restrict__ Blo,
        float* __restrict__ C, int K, int NC,
        const float* __restrict__ bias, const float* __restrict__ resid,
        const int* __restrict__ maskTok,
        uint32_t* __restrict__ outHi, uint32_t* __restrict__ outLo,
        float* __restrict__ oq, float* __restrict__ ok, float* __restrict__ ov) {
    extern __shared__ uint32_t sm[];
    const int tid = threadIdx.x;
    const int lane = tid & 31, warp = tid >> 5;
    const int wm = warp & 1, wn = warp >> 1;
    const int g = lane >> 2, tq = lane & 3;
    const int NS = K >> 5;
    const size_t aBase = (size_t)blockIdx.y * NS * 2048;
    const size_t bBase = (size_t)blockIdx.x * NS * 2048;
    const uint32_t smBase = (uint32_t)__cvta_generic_to_shared(sm);

    float acc[4][4][4];
    #pragma unroll
    for (int mt = 0; mt < 4; mt++)
        #pragma unroll
        for (int nt = 0; nt < 4; nt++)
            #pragma unroll
            for (int r = 0; r < 4; r++) acc[mt][nt][r] = 0.f;

    auto issue = [&](int s) {
        uint32_t d = smBase + (s % 3) * 32768 + tid * 16;
        const uint32_t* a1 = Ahi + aBase + (size_t)s * 2048 + tid * 4;
        const uint32_t* a2 = Alo + aBase + (size_t)s * 2048 + tid * 4;
        const uint32_t* b1 = Bhi + bBase + (size_t)s * 2048 + tid * 4;
        const uint32_t* b2 = Blo + bBase + (size_t)s * 2048 + tid * 4;
        cp16(d,          a1); cp16(d + 4096,  a1 + 1024);
        cp16(d + 8192,   a2); cp16(d + 12288, a2 + 1024);
        cp16(d + 16384,  b1); cp16(d + 20480, b1 + 1024);
        cp16(d + 24576,  b2); cp16(d + 28672, b2 + 1024);
    };

    issue(0); cp_commit();
    issue(1); cp_commit();

    for (int s = 0; s < NS; s++) {
        if (s + 1 < NS) cp_wait<1>(); else cp_wait<0>();
        __syncthreads();
        if (s + 2 < NS) { issue(s + 2); cp_commit(); }
        int base = (s % 3) * 8192;
        #pragma unroll
        for (int kb = 0; kb < 2; kb++) {
            uint4 Ah[4], Al[4]; uint2 Bh[4], Bl[4];
            #pragma unroll
            for (int mt = 0; mt < 4; mt++) {
                int blk = base + ((wm * 4 + mt) * 2 + kb) * 128 + lane * 4;
                Ah[mt] = *(uint4*)&sm[blk];
                Al[mt] = *(uint4*)&sm[blk + 2048];
            }
            #pragma unroll
            for (int nt = 0; nt < 4; nt++) {
                int bo = base + 4096 + (kb * 16 + wn * 4 + nt) * 64 + lane * 2;
                Bh[nt] = *(uint2*)&sm[bo];
                Bl[nt] = *(uint2*)&sm[bo + 2048];
            }
            #pragma unroll
            for (int mt = 0; mt < 4; mt++)
                #pragma unroll
                for (int nt = 0; nt < 4; nt++)
                    mma_bf16(acc[mt][nt], Ah[mt], Bh[nt]);
            #pragma unroll
            for (int mt = 0; mt < 4; mt++)
                #pragma unroll
                for (int nt = 0; nt < 4; nt++)
                    mma_bf16(acc[mt][nt], Ah[mt], Bl[nt]);
            #pragma unroll
            for (int mt = 0; mt < 4; mt++)
                #pragma unroll
                for (int nt = 0; nt < 4; nt++)
                    mma_bf16(acc[mt][nt], Al[mt], Bh[nt]);
        }
    }

    const long rowBase = (long)blockIdx.y * 128;
    const int colBase = blockIdx.x * 128;

    if (OUT == 1) {
        #pragma unroll
        for (int mt = 0; mt < 4; mt++) {
            float tv[4][4];
            #pragma unroll
            for (int nt = 0; nt < 4; nt++) {
                int c = colBase + wn * 32 + nt * 8 + 2 * tq;
                float b0 = bias[c], b1 = bias[c + 1];
                tv[nt][0] = gelu_tanh(acc[mt][nt][0] + b0);
                tv[nt][1] = gelu_tanh(acc[mt][nt][1] + b1);
                tv[nt][2] = gelu_tanh(acc[mt][nt][2] + b0);
                tv[nt][3] = gelu_tanh(acc[mt][nt][3] + b1);
            }
            #pragma unroll
            for (int ntp = 0; ntp < 2; ntp++) {
                uint4 hv, lv;
                split_pack(tv[2*ntp][0],   tv[2*ntp][1],   hv.x, lv.x);
                split_pack(tv[2*ntp][2],   tv[2*ntp][3],   hv.y, lv.y);
                split_pack(tv[2*ntp+1][0], tv[2*ntp+1][1], hv.z, lv.z);
                split_pack(tv[2*ntp+1][2], tv[2*ntp+1][3], hv.w, lv.w);
                size_t I = ((size_t)blockIdx.y * (NC >> 5) + blockIdx.x * 4 + wn) * 2048
                         + ((wm * 4 + mt) * 2 + ntp) * 128 + g * 16 + tq * 4;
                *(uint4*)&outHi[I] = hv;
                *(uint4*)&outLo[I] = lv;
            }
        }
        return;
    }

    if (EPI == 6) {
        int mat = colBase >> 9;
        int cc0 = colBase & 511;
        float* dst = (mat == 0) ? oq : (mat == 1) ? ok : ov;
        #pragma unroll
        for (int mt = 0; mt < 4; mt++) {
            long r0 = rowBase + wm * 64 + mt * 16 + g;
            long r1 = r0 + 8;
            float m0 = 1.f, m1 = 1.f;
            if (mat == 1) {
                m0 = (maskTok[r0] > 0) ? 1.f : 0.f;
                m1 = (maskTok[r1] > 0) ? 1.f : 0.f;
            }
            #pragma unroll
            for (int nt = 0; nt < 4; nt++) {
                int c = cc0 + wn * 32 + nt * 8 + 2 * tq;
                float v0 = acc[mt][nt][0], v1 = acc[mt][nt][1];
                float v2 = acc[mt][nt][2], v3 = acc[mt][nt][3];
                if (mat == 0) {
                    v0 = fmaxf(v0, 0.f) + KEPS; v1 = fmaxf(v1, 0.f) + KEPS;
                    v2 = fmaxf(v2, 0.f) + KEPS; v3 = fmaxf(v3, 0.f) + KEPS;
                } else if (mat == 1) {
                    v0 = (fmaxf(v0, 0.f) + KEPS) * m0; v1 = (fmaxf(v1, 0.f) + KEPS) * m0;
                    v2 = (fmaxf(v2, 0.f) + KEPS) * m1; v3 = (fmaxf(v3, 0.f) + KEPS) * m1;
                }
                float2 o0 = {v0, v1}, o1 = {v2, v3};
                *(float2*)&dst[(size_t)r0 * 512 + c] = o0;
                *(float2*)&dst[(size_t)r1 * 512 + c] = o1;
            }
        }
        return;
    }

    #pragma unroll
    for (int mt = 0; mt < 4; mt++) {
        long r0 = rowBase + wm * 64 + mt * 16 + g;
        long r1 = r0 + 8;
        #pragma unroll
        for (int nt = 0; nt < 4; nt++) {
            int c = colBase + wn * 32 + nt * 8 + 2 * tq;
            float v0 = acc[mt][nt][0], v1 = acc[mt][nt][1];
            float v2 = acc[mt][nt][2], v3 = acc[mt][nt][3];
            if (EPI == 4) {
                float b0 = bias[c], b1 = bias[c + 1];
                v0 += b0; v1 += b1; v2 += b0; v3 += b1;
            }
            v0 += resid[(size_t)r0 * NC + c];
            v1 += resid[(size_t)r0 * NC + c + 1];
            v2 += resid[(size_t)r1 * NC + c];
            v3 += resid[(size_t)r1 * NC + c + 1];
            float2 o0 = {v0, v1}, o1 = {v2, v3};
            *(float2*)&C[(size_t)r0 * NC + c] = o0;
            *(float2*)&C[(size_t)r1 * NC + c] = o1;
        }
    }
}

// ---------------- kv = phik^T @ v, z = sum phik ----------------
#define KV_SPLITS 32
__global__ void kv_kernel(const float* __restrict__ phik,
                          const float* __restrict__ v,
                          float* __restrict__ kv, float* __restrict__ z) {
    int bh = blockIdx.x, split = blockIdx.y;
    int b = bh >> 3, h = bh & 7;
    const int CH = Sz / KV_SPLITS;
    int s0 = split * CH;
    __shared__ float ks[32][64];
    __shared__ float vs[32][64];
    int tid = threadIdx.x;
    int tx = tid & 15, ty = tid >> 4;
    float acc[4][4];
    #pragma unroll
    for (int i = 0; i < 4; i++)
        #pragma unroll
        for (int j = 0; j < 4; j++) acc[i][j] = 0.f;
    float zacc[4] = {0.f, 0.f, 0.f, 0.f};
    for (int c = 0; c < CH; c += 32) {
        #pragma unroll
        for (int r = 0; r < 2; r++) {
            int f4 = tid + r * 256;
            int row = f4 >> 4, col = (f4 & 15) * 4;
            size_t base = ((size_t)(b * Sz + s0 + c + row)) * Ez + h * 64 + col;
            *(float4*)&ks[row][col] = *(const float4*)&phik[base];
            *(float4*)&vs[row][col] = *(const float4*)&v[base];
        }
        __syncthreads();
        #pragma unroll
        for (int s = 0; s < 32; s++) {
            float a[4], bb[4];
            #pragma unroll
            for (int i = 0; i < 4; i++) { a[i] = ks[s][ty * 4 + i]; bb[i] = vs[s][tx * 4 + i]; }
            #pragma unroll
            for (int i = 0; i < 4; i++)
                #pragma unroll
                for (int j = 0; j < 4; j++) acc[i][j] = fmaf(a[i], bb[j], acc[i][j]);
            if (tx == 0)
                #pragma unroll
                for (int i = 0; i < 4; i++) zacc[i] += a[i];
        }
        __syncthreads();
    }
    float* kvp = kv + bh * Dz * Dz;
    #pragma unroll
    for (int i = 0; i < 4; i++)
        #pragma unroll
        for (int j = 0; j < 4; j++)
            atomicAdd(&kvp[(ty * 4 + i) * 64 + tx * 4 + j], acc[i][j]);
    if (tx == 0)
        #pragma unroll
        for (int i = 0; i < 4; i++)
            atomicAdd(&z[bh * 64 + ty * 4 + i], zacc[i]);
}

// ---------------- numden v3: m-loop unrolled x4 with float4 p-loads --------
__global__ void numden_split(const float* __restrict__ phiq,
                             const float* __restrict__ kv,
                             const float* __restrict__ z,
                             uint32_t* __restrict__ outHi,
                             uint32_t* __restrict__ outLo) {
    int bh = blockIdx.x, chunk = blockIdx.y;
    int b = bh >> 3, h = bh & 7;
    __shared__ float kvs[64][68];
    __shared__ float zs[64];
    __shared__ float buf[64][68];
    int tid = threadIdx.x;
    int s0 = chunk * 64;

    for (int idx = tid; idx < 4096; idx += 256)
        kvs[idx >> 6][idx & 63] = kv[bh * Dz * Dz + idx];
    if (tid < 64) zs[tid] = z[bh * 64 + tid];
    {
        int r = tid >> 2, c4 = (tid & 3) * 16;
        size_t base = ((size_t)(b * Sz + s0 + r)) * Ez + h * 64 + c4;
        #pragma unroll
        for (int q = 0; q < 4; q++)
            *(float4*)&buf[r][c4 + q * 4] = *(const float4*)&phiq[base + q * 4];
    }
    __syncthreads();

    const int row = tid >> 2, cg = (tid & 3) * 16;
    float acc[16];
    #pragma unroll
    for (int j = 0; j < 16; j++) acc[j] = 0.f;
    float den = 0.f;
    #pragma unroll 4
    for (int m4 = 0; m4 < 64; m4 += 4) {
        float4 p4 = *(const float4*)&buf[row][m4];
        float4 z4 = *(const float4*)&zs[m4];
        den = fmaf(p4.x, z4.x, den);
        den = fmaf(p4.y, z4.y, den);
        den = fmaf(p4.z, z4.z, den);
        den = fmaf(p4.w, z4.w, den);
        #pragma unroll
        for (int mm = 0; mm < 4; mm++) {
            float p = (mm == 0) ? p4.x : (mm == 1) ? p4.y : (mm == 2) ? p4.z : p4.w;
            #pragma unroll
            for (int q = 0; q < 4; q++) {
                float4 k4 = *(const float4*)&kvs[m4 + mm][cg + q * 4];
                acc[q * 4 + 0] = fmaf(p, k4.x, acc[q * 4 + 0]);
                acc[q * 4 + 1] = fmaf(p, k4.y, acc[q * 4 + 1]);
                acc[q * 4 + 2] = fmaf(p, k4.z, acc[q * 4 + 2]);
                acc[q * 4 + 3] = fmaf(p, k4.w, acc[q * 4 + 3]);
            }
        }
    }
    __syncthreads();
    float inv = 1.f / den;
    #pragma unroll
    for (int q = 0; q < 4; q++) {
        float4 o;
        o.x = acc[q * 4 + 0] * inv; o.y = acc[q * 4 + 1] * inv;
        o.z = acc[q * 4 + 2] * inv; o.w = acc[q * 4 + 3] * inv;
        *(float4*)&buf[row][cg + q * 4] = o;
    }
    __syncthreads();

    int g = tid & 7, halfRun = (tid >> 3) & 1, kb = (tid >> 4) & 1;
    int s2 = (tid >> 5) & 1, mtl = tid >> 6;
    long rowTile = ((long)b * Sz + chunk * 64) >> 7;
    int mtG = (chunk & 1) * 4 + mtl;
    int stage = h * 2 + s2;
    uint32_t hi[8], lo[8];
    #pragma unroll
    for (int o = 0; o < 8; o++) {
        int tqv = halfRun * 2 + (o >> 2);
        int kbit = (o >> 1) & 1, rbit = o & 1;
        int rl = mtl * 16 + g + 8 * rbit;
        int cl = s2 * 32 + kb * 16 + 2 * tqv + 8 * kbit;
        split_pack(buf[rl][cl], buf[rl][cl + 1], hi[o], lo[o]);
    }
    size_t I = ((size_t)(rowTile * 16 + stage)) * 2048
             + (mtG * 2 + kb) * 128 + g * 16 + halfRun * 8;
    *(uint4*)&outHi[I]     = *(uint4*)&hi[0];
    *(uint4*)&outHi[I + 4] = *(uint4*)&hi[4];
    *(uint4*)&outLo[I]     = *(uint4*)&lo[0];
    *(uint4*)&outLo[I + 4] = *(uint4*)&lo[4];
}

// ---------------- host ----------------
extern "C" void kernel_launch(void* const* d_in, const int* in_sizes, int n_in,
                              void* d_out, int out_size) {
    const int*   inputs    = (const int*)  d_in[0];
    const float* embed     = (const float*)d_in[1];
    const float* ln1_scale = (const float*)d_in[2];
    const float* ln1_bias  = (const float*)d_in[3];
    const float* wq        = (const float*)d_in[4];
    const float* wk        = (const float*)d_in[5];
    const float* wv        = (const float*)d_in[6];
    const float* wo        = (const float*)d_in[7];
    const float* ln2_scale = (const float*)d_in[8];
    const float* ln2_bias  = (const float*)d_in[9];
    const float* w1        = (const float*)d_in[10];
    const float* b1        = (const float*)d_in[11];
    const float* w2        = (const float*)d_in[12];
    const float* b2        = (const float*)d_in[13];
    const float* lnf_scale = (const float*)d_in[14];
    const float* lnf_bias  = (const float*)d_in[15];
    float* out = (float*)d_out;

    static float *px = nullptr, *pq, *pk, *pv, *pkv, *pz;
    static uint32_t *hAhi, *hAlo, *ndhi, *ndlo, *pthi, *ptlo, *whi, *wlo;
    if (!px) {
        cudaGetSymbolAddress((void**)&px,   g_x);
        cudaGetSymbolAddress((void**)&pq,   g_phiq);
        cudaGetSymbolAddress((void**)&pk,   g_phik);
        cudaGetSymbolAddress((void**)&pv,   g_v);
        cudaGetSymbolAddress((void**)&pkv,  g_kv);
        cudaGetSymbolAddress((void**)&pz,   g_z);
        cudaGetSymbolAddress((void**)&hAhi, g_hAhi);
        cudaGetSymbolAddress((void**)&hAlo, g_hAlo);
        cudaGetSymbolAddress((void**)&ndhi, g_ndhi);
        cudaGetSymbolAddress((void**)&ndlo, g_ndlo);
        cudaGetSymbolAddress((void**)&pthi, g_pthi);
        cudaGetSymbolAddress((void**)&ptlo, g_ptlo);
        cudaGetSymbolAddress((void**)&whi,  g_whi);
        cudaGetSymbolAddress((void**)&wlo,  g_wlo);
        cudaFuncSetAttribute(gemm_tc<6,0>, cudaFuncAttributeMaxDynamicSharedMemorySize, SMEM_BYTES);
        cudaFuncSetAttribute(gemm_tc<5,0>, cudaFuncAttributeMaxDynamicSharedMemorySize, SMEM_BYTES);
        cudaFuncSetAttribute(gemm_tc<3,1>, cudaFuncAttributeMaxDynamicSharedMemorySize, SMEM_BYTES);
        cudaFuncSetAttribute(gemm_tc<4,0>, cudaFuncAttributeMaxDynamicSharedMemorySize, SMEM_BYTES);
    }

    dim3 gQKV(12, Nrows / 128);
    dim3 gE(4, Nrows / 128);
    dim3 gM(16, Nrows / 128);
    dim3 gKV(Bz * Hz, KV_SPLITS);
    dim3 gND(Bz * Hz, Sz / 64);

    // our launches: 0 split_qkv, 1 zero_all, 2 embed, 3 ln_split (ncu -s 5)
    split_qkv<<<dim3(2, 32, 3 * Lz), 256>>>(wq, wk, wv, whi + OFQ, wlo + OFQ);
    zero_all_kernel<<<(Lz * KVSZ + 255) / 256, 256>>>(pkv, pz);
    embed_pe_kernel<<<(Nrows * Ez + 255) / 256, 256>>>(inputs, embed, px);
    layernorm_split<<<Nrows / 16, 256>>>(px, hAhi, hAlo, ln1_scale, ln1_bias);
    gemm_tc<6,0><<<gQKV, 256, SMEM_BYTES>>>(hAhi, hAlo, whi + OFQ, wlo + OFQ,
                                            nullptr, Ez, 512, nullptr, nullptr, inputs,
                                            nullptr, nullptr, pq, pk, pv);
    split_w<<<dim3(2, 32, Lz), 256>>>(wo, whi + OO, wlo + OO, Ez, Ez, (size_t)Ez*Ez, 131072);
    split_w<<<dim3(8, 32, Lz), 256>>>(w1, whi + O1, wlo + O1, Ez, Mz, (size_t)Ez*Mz, 524288);
    split_w<<<dim3(2, 128, Lz), 256>>>(w2, whi + O2, wlo + O2, Mz, Ez, (size_t)Mz*Ez, 524288);

    for (int l = 0; l < Lz; l++) {
        const uint32_t* fqh = whi + OFQ + (size_t)l * 393216;
        const uint32_t* fql = wlo + OFQ + (size_t)l * 393216;
        const uint32_t* woh = whi + OO + (size_t)l * 131072;
        const uint32_t* wol = wlo + OO + (size_t)l * 131072;
        const uint32_t* w1h = whi + O1 + (size_t)l * 524288;
        const uint32_t* w1l = wlo + O1 + (size_t)l * 524288;
        const uint32_t* w2h = whi + O2 + (size_t)l * 524288;
        const uint32_t* w2l = wlo + O2 + (size_t)l * 524288;
        float* kvL = pkv + (size_t)l * KVSZ;
        float* zL  = pz  + (size_t)l * ZSZ;

        if (l > 0) {
            layernorm_split<<<Nrows / 16, 256>>>(px, hAhi, hAlo,
                                                 ln1_scale + l * Ez, ln1_bias + l * Ez);
            gemm_tc<6,0><<<gQKV, 256, SMEM_BYTES>>>(hAhi, hAlo, fqh, fql,
                                                    nullptr, Ez, 512, nullptr, nullptr, inputs,
                                                    nullptr, nullptr, pq, pk, pv);
        }
        kv_kernel<<<gKV, 256>>>(pk, pv, kvL, zL);
        numden_split<<<gND, 256>>>(pq, kvL, zL, ndhi, ndlo);
        gemm_tc<5,0><<<gE, 256, SMEM_BYTES>>>(ndhi, ndlo, woh, wol, px, Ez, Ez,
                                              nullptr, px, nullptr, nullptr, nullptr,
                                              nullptr, nullptr, nullptr);
        layernorm_split<<<Nrows / 16, 256>>>(px, hAhi, hAlo,
                                             ln2_scale + l * Ez, ln2_bias + l * Ez);
        gemm_tc<3,1><<<gM, 256, SMEM_BYTES>>>(hAhi, hAlo, w1h, w1l, nullptr, Ez, Mz,
                                              b1 + (size_t)l * Mz, nullptr, nullptr,
                                              pthi, ptlo, nullptr, nullptr, nullptr);
        gemm_tc<4,0><<<gE, 256, SMEM_BYTES>>>(pthi, ptlo, w2h, w2l, px, Mz, Ez,
                                              b2 + (size_t)l * Ez, px, nullptr,
                                              nullptr, nullptr, nullptr, nullptr, nullptr);
    }

    layernorm_kernel<<<Nrows, 256>>>(px, out, lnf_scale, lnf_bias);
}

// round 16
// speedup vs baseline: 1.1431x; 1.1157x over previous
#include <cuda_runtime.h>
#include <cuda_bf16.h>
#include <math.h>
#include <stdint.h>

#define Bz 4
#define Sz 4096
#define Ez 512
#define Hz 8
#define Dz 64
#define Mz 2048
#define Lz 6
#define Nrows (Bz*Sz)
#define LN_EPS 1e-6f
#define KEPS 1e-3f
#define KVSZ (Bz*Hz*Dz*Dz)
#define ZSZ  (Bz*Hz*Dz)

// ---------------- device scratch ----------------
__device__ float g_x[Nrows*Ez];
__device__ float g_phiq[Nrows*Ez];
__device__ float g_phik[Nrows*Ez];
__device__ float g_v[Nrows*Ez];
__device__ float g_kv[Lz*KVSZ];
__device__ float g_z[Lz*ZSZ];
__device__ __align__(16) uint32_t g_hAhi[Nrows*256];
__device__ __align__(16) uint32_t g_hAlo[Nrows*256];
__device__ __align__(16) uint32_t g_ndhi[Nrows*256];
__device__ __align__(16) uint32_t g_ndlo[Nrows*256];
__device__ __align__(16) uint32_t g_pthi[Nrows*1024];
__device__ __align__(16) uint32_t g_ptlo[Nrows*1024];
#define OFQ 0
#define OO  2359296
#define O1  3145728
#define O2  6291456
#define WTOT 9437184
__device__ __align__(16) uint32_t g_whi[WTOT];
__device__ __align__(16) uint32_t g_wlo[WTOT];

// ---------------- helpers ----------------
__device__ __forceinline__ void split_pack(float x0, float x1,
                                           uint32_t& hi, uint32_t& lo) {
    __nv_bfloat162 h = __floats2bfloat162_rn(x0, x1);
    float r0 = x0 - __bfloat162float(h.x);
    float r1 = x1 - __bfloat162float(h.y);
    __nv_bfloat162 l = __floats2bfloat162_rn(r0, r1);
    hi = *reinterpret_cast<uint32_t*>(&h);
    lo = *reinterpret_cast<uint32_t*>(&l);
}
__device__ __forceinline__ void mma_bf16(float* c, uint4 a, uint2 b) {
    asm volatile(
        "mma.sync.aligned.m16n8k16.row.col.f32.bf16.bf16.f32 "
        "{%0,%1,%2,%3}, {%4,%5,%6,%7}, {%8,%9}, {%0,%1,%2,%3};"
        : "+f"(c[0]), "+f"(c[1]), "+f"(c[2]), "+f"(c[3])
        : "r"(a.x), "r"(a.y), "r"(a.z), "r"(a.w), "r"(b.x), "r"(b.y));
}
__device__ __forceinline__ float warp_sum(float v) {
    #pragma unroll
    for (int o = 16; o; o >>= 1) v += __shfl_xor_sync(0xffffffffu, v, o);
    return v;
}
__device__ __forceinline__ float gelu_tanh(float x) {
    float x3 = x * x * x;
    return 0.5f * x * (1.f + tanhf(0.7978845608028654f * (x + 0.044715f * x3)));
}
__device__ __forceinline__ void cp16(uint32_t dst, const void* src) {
    asm volatile("cp.async.cg.shared.global [%0], [%1], 16;\n" :: "r"(dst), "l"(src));
}
__device__ __forceinline__ void cp_commit() { asm volatile("cp.async.commit_group;\n"); }
template<int N>
__device__ __forceinline__ void cp_wait() {
    asm volatile("cp.async.wait_group %0;\n" :: "n"(N));
}

// ---------------- fused qkv weight split ----------------
__global__ void split_qkv(const float* __restrict__ wq, const float* __restrict__ wk,
                          const float* __restrict__ wv,
                          uint32_t* __restrict__ hi, uint32_t* __restrict__ lo) {
    int z = blockIdx.z, l = z / 3, m = z % 3;
    const float* Wl = (m == 0 ? wq : m == 1 ? wk : wv) + (size_t)l * Ez * Ez;
    uint32_t* hiL = hi + (size_t)l * 393216 + (size_t)m * 131072;
    uint32_t* loL = lo + (size_t)l * 393216 + (size_t)m * 131072;
    int c = blockIdx.x * 256 + threadIdx.x;
    int kb = blockIdx.y;
    int cb = c >> 7, nb = (c >> 3) & 15, g = c & 7;
    int stage = kb >> 1, kbS = kb & 1;
    uint32_t h8[8], l8[8];
    #pragma unroll
    for (int o = 0; o < 8; o++) {
        int tq = o >> 1, hb = o & 1;
        int k = kb * 16 + 2 * tq + 8 * hb;
        split_pack(Wl[(size_t)k * Ez + c], Wl[(size_t)(k + 1) * Ez + c], h8[o], l8[o]);
    }
    size_t I = ((size_t)(cb * 16 + stage)) * 2048 + (kbS * 16 + nb) * 64 + g * 8;
    *(uint4*)&hiL[I]     = *(uint4*)&h8[0];
    *(uint4*)&hiL[I + 4] = *(uint4*)&h8[4];
    *(uint4*)&loL[I]     = *(uint4*)&l8[0];
    *(uint4*)&loL[I + 4] = *(uint4*)&l8[4];
}

// ---------------- generic weight split ----------------
__global__ void split_w(const float* __restrict__ W,
                        uint32_t* __restrict__ hi, uint32_t* __restrict__ lo,
                        int K, int NC, size_t wStrideL, size_t oStrideL) {
    int l = blockIdx.z;
    const float* Wl = W + (size_t)l * wStrideL;
    uint32_t* hiL = hi + (size_t)l * oStrideL;
    uint32_t* loL = lo + (size_t)l * oStrideL;
    int c = blockIdx.x * 256 + threadIdx.x;
    int kb = blockIdx.y;
    int cb = c >> 7, nb = (c >> 3) & 15, g = c & 7;
    int stage = kb >> 1, kbS = kb & 1;
    uint32_t h8[8], l8[8];
    #pragma unroll
    for (int o = 0; o < 8; o++) {
        int tq = o >> 1, hb = o & 1;
        int k = kb * 16 + 2 * tq + 8 * hb;
        split_pack(Wl[(size_t)k * NC + c], Wl[(size_t)(k + 1) * NC + c], h8[o], l8[o]);
    }
    size_t I = ((size_t)(cb * (K >> 5) + stage)) * 2048 + (kbS * 16 + nb) * 64 + g * 8;
    *(uint4*)&hiL[I]     = *(uint4*)&h8[0];
    *(uint4*)&hiL[I + 4] = *(uint4*)&h8[4];
    *(uint4*)&loL[I]     = *(uint4*)&l8[0];
    *(uint4*)&loL[I + 4] = *(uint4*)&l8[4];
}

// ---------------- embedding + PE ----------------
__global__ void embed_pe_kernel(const int* __restrict__ inp,
                                const float* __restrict__ emb,
                                float* __restrict__ x) {
    int idx = blockIdx.x * blockDim.x + threadIdx.x;
    if (idx >= Nrows * Ez) return;
    int e = idx & (Ez - 1);
    int n = idx >> 9;
    int s = n & (Sz - 1);
    int tok = inp[n];
    int j = (e >> 1) * 2;
    const float c = -9.210340371976184f / (float)Ez;
    float ang = (float)s * expf((float)j * c);
    float pe = (e & 1) ? cosf(ang) : sinf(ang);
    x[idx] = emb[(size_t)tok * Ez + e] + pe;
}

// ---------------- zero all kv/z slices ----------------
__global__ void zero_all_kernel(float* kv, float* z) {
    int i = blockIdx.x * blockDim.x + threadIdx.x;
    if (i < Lz * KVSZ) kv[i] = 0.f;
    if (i < Lz * ZSZ) z[i] = 0.f;
}

// ---------------- final plain layernorm ----------------
__device__ __forceinline__ float block_sum(float val, float* red) {
    __syncthreads();
    int t = threadIdx.x;
    #pragma unroll
    for (int o = 16; o; o >>= 1) val += __shfl_down_sync(0xffffffffu, val, o);
    if ((t & 31) == 0) red[t >> 5] = val;
    __syncthreads();
    if (t < 32) {
        float r = (t < 8) ? red[t] : 0.f;
        #pragma unroll
        for (int o = 4; o; o >>= 1) r += __shfl_down_sync(0xffffffffu, r, o);
        if (t == 0) red[0] = r;
    }
    __syncthreads();
    return red[0];
}
__global__ void layernorm_kernel(const float* __restrict__ in,
                                 float* __restrict__ out,
                                 const float* __restrict__ scale,
                                 const float* __restrict__ bias) {
    __shared__ float red[32];
    int n = blockIdx.x;
    int t = threadIdx.x;
    const float* row = in + (size_t)n * Ez;
    float2 v = *(const float2*)&row[t * 2];
    float mu = block_sum(v.x + v.y, red) * (1.f / Ez);
    float dx = v.x - mu, dy = v.y - mu;
    float var = block_sum(dx * dx + dy * dy, red) * (1.f / Ez);
    float rs = rsqrtf(var + LN_EPS);
    float2 o;
    o.x = dx * rs * scale[t * 2 + 0] + bias[t * 2 + 0];
    o.y = dy * rs * scale[t * 2 + 1] + bias[t * 2 + 1];
    *(float2*)&out[(size_t)n * Ez + t * 2] = o;
}

// ---------------- layernorm -> split-permuted (16 rows/block) ----------------
__global__ void layernorm_split(const float* __restrict__ in,
                                uint32_t* __restrict__ outHi,
                                uint32_t* __restrict__ outLo,
                                const float* __restrict__ scale,
                                const float* __restrict__ bias) {
    __shared__ float nrm[16][516];
    int tid = threadIdx.x;
    int warp = tid >> 5, lane = tid & 31;
    long n0 = (long)blockIdx.x * 16;
    #pragma unroll
    for (int rr = 0; rr < 2; rr++) {
        int r = warp * 2 + rr;
        const float* row = in + (n0 + r) * Ez;
        float4 v[4];
        float s = 0.f;
        #pragma unroll
        for (int q = 0; q < 4; q++) {
            v[q] = *(const float4*)&row[lane * 4 + q * 128];
            s += v[q].x + v[q].y + v[q].z + v[q].w;
        }
        float mu = warp_sum(s) * (1.f / Ez);
        float vr = 0.f;
        #pragma unroll
        for (int q = 0; q < 4; q++) {
            float a = v[q].x - mu, b = v[q].y - mu, c = v[q].z - mu, d = v[q].w - mu;
            vr += a * a + b * b + c * c + d * d;
        }
        float rs = rsqrtf(warp_sum(vr) * (1.f / Ez) + LN_EPS);
        #pragma unroll
        for (int q = 0; q < 4; q++) {
            int c = lane * 4 + q * 128;
            float4 sc = *(const float4*)&scale[c];
            float4 bi = *(const float4*)&bias[c];
            float4 o;
            o.x = (v[q].x - mu) * rs * sc.x + bi.x;
            o.y = (v[q].y - mu) * rs * sc.y + bi.y;
            o.z = (v[q].z - mu) * rs * sc.z + bi.z;
            o.w = (v[q].w - mu) * rs * sc.w + bi.w;
            *(float4*)&nrm[r][c] = o;
        }
    }
    __syncthreads();
    int g = tid & 7, kb = (tid >> 3) & 1, stage = tid >> 4;
    uint32_t hi[16], lo[16];
    #pragma unroll
    for (int o = 0; o < 16; o++) {
        int tq = o >> 2, kbit = (o >> 1) & 1, rbit = o & 1;
        int c = stage * 32 + kb * 16 + 2 * tq + 8 * kbit;
        int rl = g + 8 * rbit;
        split_pack(nrm[rl][c], nrm[rl][c + 1], hi[o], lo[o]);
    }
    size_t I = ((size_t)((blockIdx.x >> 3) * 16 + stage)) * 2048
             + ((blockIdx.x & 7) * 2 + kb) * 128 + g * 16;
    *(uint4*)&outHi[I]      = *(uint4*)&hi[0];
    *(uint4*)&outHi[I + 4]  = *(uint4*)&hi[4];
    *(uint4*)&outHi[I + 8]  = *(uint4*)&hi[8];
    *(uint4*)&outHi[I + 12] = *(uint4*)&hi[12];
    *(uint4*)&outLo[I]      = *(uint4*)&lo[0];
    *(uint4*)&outLo[I + 4]  = *(uint4*)&lo[4];
    *(uint4*)&outLo[I + 8]  = *(uint4*)&lo[8];
    *(uint4*)&outLo[I + 12] = *(uint4*)&lo[12];
}

// ---------------- tensor-core GEMM (R8 config) ----------------
#define SMEM_BYTES 98304
template<int EPI, int OUT>
__global__ void __launch_bounds__(256, 2)
gemm_tc(const uint32_t* __restrict__ Ahi, const uint32_t* __restrict__ Alo,
        const uint32_t* __restrict__ Bhi, const uint32_t* __restrict__ Blo,
        float* __restrict__ C, int K, int NC,
        const float* __restrict__ bias, const float* __restrict__ resid,
        const int* __restrict__ maskTok,
        uint32_t* __restrict__ outHi, uint32_t* __restrict__ outLo,
        float* __restrict__ oq, float* __restrict__ ok, float* __restrict__ ov) {
    extern __shared__ uint32_t sm[];
    const int tid = threadIdx.x;
    const int lane = tid & 31, warp = tid >> 5;
    const int wm = warp & 1, wn = warp >> 1;
    const int g = lane >> 2, tq = lane & 3;
    const int NS = K >> 5;
    const size_t aBase = (size_t)blockIdx.y * NS * 2048;
    const size_t bBase = (size_t)blockIdx.x * NS * 2048;
    const uint32_t smBase = (uint32_t)__cvta_generic_to_shared(sm);

    float acc[4][4][4];
    #pragma unroll
    for (int mt = 0; mt < 4; mt++)
        #pragma unroll
        for (int nt = 0; nt < 4; nt++)
            #pragma unroll
            for (int r = 0; r < 4; r++) acc[mt][nt][r] = 0.f;

    auto issue = [&](int s) {
        uint32_t d = smBase + (s % 3) * 32768 + tid * 16;
        const uint32_t* a1 = Ahi + aBase + (size_t)s * 2048 + tid * 4;
        const uint32_t* a2 = Alo + aBase + (size_t)s * 2048 + tid * 4;
        const uint32_t* b1 = Bhi + bBase + (size_t)s * 2048 + tid * 4;
        const uint32_t* b2 = Blo + bBase + (size_t)s * 2048 + tid * 4;
        cp16(d,          a1); cp16(d + 4096,  a1 + 1024);
        cp16(d + 8192,   a2); cp16(d + 12288, a2 + 1024);
        cp16(d + 16384,  b1); cp16(d + 20480, b1 + 1024);
        cp16(d + 24576,  b2); cp16(d + 28672, b2 + 1024);
    };

    issue(0); cp_commit();
    issue(1); cp_commit();

    for (int s = 0; s < NS; s++) {
        if (s + 1 < NS) cp_wait<1>(); else cp_wait<0>();
        __syncthreads();
        if (s + 2 < NS) { issue(s + 2); cp_commit(); }
        int base = (s % 3) * 8192;
        #pragma unroll
        for (int kb = 0; kb < 2; kb++) {
            uint4 Ah[4], Al[4]; uint2 Bh[4], Bl[4];
            #pragma unroll
            for (int mt = 0; mt < 4; mt++) {
                int blk = base + ((wm * 4 + mt) * 2 + kb) * 128 + lane * 4;
                Ah[mt] = *(uint4*)&sm[blk];
                Al[mt] = *(uint4*)&sm[blk + 2048];
            }
            #pragma unroll
            for (int nt = 0; nt < 4; nt++) {
                int bo = base + 4096 + (kb * 16 + wn * 4 + nt) * 64 + lane * 2;
                Bh[nt] = *(uint2*)&sm[bo];
                Bl[nt] = *(uint2*)&sm[bo + 2048];
            }
            #pragma unroll
            for (int mt = 0; mt < 4; mt++)
                #pragma unroll
                for (int nt = 0; nt < 4; nt++)
                    mma_bf16(acc[mt][nt], Ah[mt], Bh[nt]);
            #pragma unroll
            for (int mt = 0; mt < 4; mt++)
                #pragma unroll
                for (int nt = 0; nt < 4; nt++)
                    mma_bf16(acc[mt][nt], Ah[mt], Bl[nt]);
            #pragma unroll
            for (int mt = 0; mt < 4; mt++)
                #pragma unroll
                for (int nt = 0; nt < 4; nt++)
                    mma_bf16(acc[mt][nt], Al[mt], Bh[nt]);
        }
    }

    const long rowBase = (long)blockIdx.y * 128;
    const int colBase = blockIdx.x * 128;

    if (OUT == 1) {
        #pragma unroll
        for (int mt = 0; mt < 4; mt++) {
            float tv[4][4];
            #pragma unroll
            for (int nt = 0; nt < 4; nt++) {
                int c = colBase + wn * 32 + nt * 8 + 2 * tq;
                float b0 = bias[c], b1 = bias[c + 1];
                tv[nt][0] = gelu_tanh(acc[mt][nt][0] + b0);
                tv[nt][1] = gelu_tanh(acc[mt][nt][1] + b1);
                tv[nt][2] = gelu_tanh(acc[mt][nt][2] + b0);
                tv[nt][3] = gelu_tanh(acc[mt][nt][3] + b1);
            }
            #pragma unroll
            for (int ntp = 0; ntp < 2; ntp++) {
                uint4 hv, lv;
                split_pack(tv[2*ntp][0],   tv[2*ntp][1],   hv.x, lv.x);
                split_pack(tv[2*ntp][2],   tv[2*ntp][3],   hv.y, lv.y);
                split_pack(tv[2*ntp+1][0], tv[2*ntp+1][1], hv.z, lv.z);
                split_pack(tv[2*ntp+1][2], tv[2*ntp+1][3], hv.w, lv.w);
                size_t I = ((size_t)blockIdx.y * (NC >> 5) + blockIdx.x * 4 + wn) * 2048
                         + ((wm * 4 + mt) * 2 + ntp) * 128 + g * 16 + tq * 4;
                *(uint4*)&outHi[I] = hv;
                *(uint4*)&outLo[I] = lv;
            }
        }
        return;
    }

    if (EPI == 6) {
        int mat = colBase >> 9;
        int cc0 = colBase & 511;
        float* dst = (mat == 0) ? oq : (mat == 1) ? ok : ov;
        #pragma unroll
        for (int mt = 0; mt < 4; mt++) {
            long r0 = rowBase + wm * 64 + mt * 16 + g;
            long r1 = r0 + 8;
            float m0 = 1.f, m1 = 1.f;
            if (mat == 1) {
                m0 = (maskTok[r0] > 0) ? 1.f : 0.f;
                m1 = (maskTok[r1] > 0) ? 1.f : 0.f;
            }
            #pragma unroll
            for (int nt = 0; nt < 4; nt++) {
                int c = cc0 + wn * 32 + nt * 8 + 2 * tq;
                float v0 = acc[mt][nt][0], v1 = acc[mt][nt][1];
                float v2 = acc[mt][nt][2], v3 = acc[mt][nt][3];
                if (mat == 0) {
                    v0 = fmaxf(v0, 0.f) + KEPS; v1 = fmaxf(v1, 0.f) + KEPS;
                    v2 = fmaxf(v2, 0.f) + KEPS; v3 = fmaxf(v3, 0.f) + KEPS;
                } else if (mat == 1) {
                    v0 = (fmaxf(v0, 0.f) + KEPS) * m0; v1 = (fmaxf(v1, 0.f) + KEPS) * m0;
                    v2 = (fmaxf(v2, 0.f) + KEPS) * m1; v3 = (fmaxf(v3, 0.f) + KEPS) * m1;
                }
                float2 o0 = {v0, v1}, o1 = {v2, v3};
                *(float2*)&dst[(size_t)r0 * 512 + c] = o0;
                *(float2*)&dst[(size_t)r1 * 512 + c] = o1;
            }
        }
        return;
    }

    #pragma unroll
    for (int mt = 0; mt < 4; mt++) {
        long r0 = rowBase + wm * 64 + mt * 16 + g;
        long r1 = r0 + 8;
        #pragma unroll
        for (int nt = 0; nt < 4; nt++) {
            int c = colBase + wn * 32 + nt * 8 + 2 * tq;
            float v0 = acc[mt][nt][0], v1 = acc[mt][nt][1];
            float v2 = acc[mt][nt][2], v3 = acc[mt][nt][3];
            if (EPI == 4) {
                float b0 = bias[c], b1 = bias[c + 1];
                v0 += b0; v1 += b1; v2 += b0; v3 += b1;
            }
            v0 += resid[(size_t)r0 * NC + c];
            v1 += resid[(size_t)r0 * NC + c + 1];
            v2 += resid[(size_t)r1 * NC + c];
            v3 += resid[(size_t)r1 * NC + c + 1];
            float2 o0 = {v0, v1}, o1 = {v2, v3};
            *(float2*)&C[(size_t)r0 * NC + c] = o0;
            *(float2*)&C[(size_t)r1 * NC + c] = o1;
        }
    }
}

// ---------------- kv = phik^T @ v, z = sum phik ----------------
#define KV_SPLITS 32
__global__ void kv_kernel(const float* __restrict__ phik,
                          const float* __restrict__ v,
                          float* __restrict__ kv, float* __restrict__ z) {
    int bh = blockIdx.x, split = blockIdx.y;
    int b = bh >> 3, h = bh & 7;
    const int CH = Sz / KV_SPLITS;
    int s0 = split * CH;
    __shared__ float ks[32][64];
    __shared__ float vs[32][64];
    int tid = threadIdx.x;
    int tx = tid & 15, ty = tid >> 4;
    float acc[4][4];
    #pragma unroll
    for (int i = 0; i < 4; i++)
        #pragma unroll
        for (int j = 0; j < 4; j++) acc[i][j] = 0.f;
    float zacc[4] = {0.f, 0.f, 0.f, 0.f};
    for (int c = 0; c < CH; c += 32) {
        #pragma unroll
        for (int r = 0; r < 2; r++) {
            int f4 = tid + r * 256;
            int row = f4 >> 4, col = (f4 & 15) * 4;
            size_t base = ((size_t)(b * Sz + s0 + c + row)) * Ez + h * 64 + col;
            *(float4*)&ks[row][col] = *(const float4*)&phik[base];
            *(float4*)&vs[row][col] = *(const float4*)&v[base];
        }
        __syncthreads();
        #pragma unroll
        for (int s = 0; s < 32; s++) {
            float a[4], bb[4];
            #pragma unroll
            for (int i = 0; i < 4; i++) { a[i] = ks[s][ty * 4 + i]; bb[i] = vs[s][tx * 4 + i]; }
            #pragma unroll
            for (int i = 0; i < 4; i++)
                #pragma unroll
                for (int j = 0; j < 4; j++) acc[i][j] = fmaf(a[i], bb[j], acc[i][j]);
            if (tx == 0)
                #pragma unroll
                for (int i = 0; i < 4; i++) zacc[i] += a[i];
        }
        __syncthreads();
    }
    float* kvp = kv + bh * Dz * Dz;
    #pragma unroll
    for (int i = 0; i < 4; i++)
        #pragma unroll
        for (int j = 0; j < 4; j++)
            atomicAdd(&kvp[(ty * 4 + i) * 64 + tx * 4 + j], acc[i][j]);
    if (tx == 0)
        #pragma unroll
        for (int i = 0; i < 4; i++)
            atomicAdd(&z[bh * 64 + ty * 4 + i], zacc[i]);
}

// ---------------- numden via tensor cores (bf16x3) --------------------------
// grid (32 bh, Sz/128*Bz/Bz... = 32 chunks of 128 rows per b), block 256.
// A = phiq[128 x 64] (rows of batch b, cols h*64..), B = kv[64 x 64].
// smem (dynamic): Ah @0 (4096 u32), Al @4096, Bh @8192 (2048), Bl @10240,
//                 zsm @12288 (64 f), den2 @12352 (256 f)
#define ND_SMEM ((12288 + 64 + 256) * 4)
__global__ void __launch_bounds__(256, 4)
numden_mma(const float* __restrict__ phiq, const float* __restrict__ kv,
           const float* __restrict__ z,
           uint32_t* __restrict__ outHi, uint32_t* __restrict__ outLo) {
    extern __shared__ uint32_t nds[];
    uint32_t* Ah = nds;
    uint32_t* Al = nds + 4096;
    uint32_t* Bh = nds + 8192;
    uint32_t* Bl = nds + 10240;
    float* zsm = (float*)(nds + 12288);
    float* den2 = zsm + 64;                     // [128][2]

    int bh = blockIdx.x, chunk = blockIdx.y;
    int b = bh >> 3, h = bh & 7;
    int tid = threadIdx.x;

    if (tid < 64) zsm[tid] = z[bh * 64 + tid];
    __syncthreads();

    // kv -> B fragment-split layout
    {
        int kb = tid >> 6, c = tid & 63;
        int nb = c >> 3, gg = c & 7;
        const float* kvp = kv + bh * 4096;
        uint32_t h8[8], l8[8];
        #pragma unroll
        for (int o = 0; o < 8; o++) {
            int tqv = o >> 1, hb = o & 1;
            int k = kb * 16 + 2 * tqv + 8 * hb;
            split_pack(kvp[k * 64 + c], kvp[(k + 1) * 64 + c], h8[o], l8[o]);
        }
        int I = kb * 512 + nb * 64 + gg * 8;
        *(uint4*)&Bh[I]     = *(uint4*)&h8[0];
        *(uint4*)&Bh[I + 4] = *(uint4*)&h8[4];
        *(uint4*)&Bl[I]     = *(uint4*)&l8[0];
        *(uint4*)&Bl[I + 4] = *(uint4*)&l8[4];
    }

    // phiq rows -> Ahi/Alo row-major packed; den partial in fp32
    {
        int r = tid >> 1, half = tid & 1;
        const float* src = phiq + ((size_t)(b * Sz + chunk * 128 + r)) * Ez
                         + h * 64 + half * 32;
        float dp = 0.f;
        #pragma unroll
        for (int q = 0; q < 8; q++) {
            float4 v4 = *(const float4*)&src[q * 4];
            int cb = half * 32 + q * 4;
            dp = fmaf(v4.x, zsm[cb], fmaf(v4.y, zsm[cb + 1],
                 fmaf(v4.z, zsm[cb + 2], fmaf(v4.w, zsm[cb + 3], dp))));
            uint32_t h0, l0, h1, l1;
            split_pack(v4.x, v4.y, h0, l0);
            split_pack(v4.z, v4.w, h1, l1);
            int I = r * 32 + half * 16 + q * 2;
            Ah[I] = h0; Ah[I + 1] = h1;
            Al[I] = l0; Al[I + 1] = l1;
        }
        den2[r * 2 + half] = dp;
    }
    __syncthreads();

    const int lane = tid & 31, warp = tid >> 5;
    const int g = lane >> 2, tq = lane & 3;
    const int rb = warp * 16;

    float acc[8][4];
    #pragma unroll
    for (int nt = 0; nt < 8; nt++)
        #pragma unroll
        for (int r = 0; r < 4; r++) acc[nt][r] = 0.f;

    #pragma unroll
    for (int kb = 0; kb < 4; kb++) {
        uint4 ah, al;
        ah.x = Ah[(rb + g) * 32 + kb * 8 + tq];
        ah.y = Ah[(rb + g + 8) * 32 + kb * 8 + tq];
        ah.z = Ah[(rb + g) * 32 + kb * 8 + tq + 4];
        ah.w = Ah[(rb + g + 8) * 32 + kb * 8 + tq + 4];
        al.x = Al[(rb + g) * 32 + kb * 8 + tq];
        al.y = Al[(rb + g + 8) * 32 + kb * 8 + tq];
        al.z = Al[(rb + g) * 32 + kb * 8 + tq + 4];
        al.w = Al[(rb + g + 8) * 32 + kb * 8 + tq + 4];
        uint2 bhf[8], blf[8];
        #pragma unroll
        for (int nt = 0; nt < 8; nt++) {
            bhf[nt] = *(uint2*)&Bh[kb * 512 + nt * 64 + lane * 2];
            blf[nt] = *(uint2*)&Bl[kb * 512 + nt * 64 + lane * 2];
        }
        #pragma unroll
        for (int nt = 0; nt < 8; nt++) mma_bf16(acc[nt], ah, bhf[nt]);
        #pragma unroll
        for (int nt = 0; nt < 8; nt++) mma_bf16(acc[nt], ah, blf[nt]);
        #pragma unroll
        for (int nt = 0; nt < 8; nt++) mma_bf16(acc[nt], al, bhf[nt]);
    }

    float inv0 = 1.f / (den2[(rb + g) * 2] + den2[(rb + g) * 2 + 1]);
    float inv1 = 1.f / (den2[(rb + g + 8) * 2] + den2[(rb + g + 8) * 2 + 1]);

    long rowTile = (long)b * (Sz / 128) + chunk;
    #pragma unroll
    for (int s2 = 0; s2 < 2; s2++) {
        #pragma unroll
        for (int ntp = 0; ntp < 2; ntp++) {
            int nA = s2 * 4 + ntp * 2, nB = nA + 1;
            uint4 hv, lv;
            split_pack(acc[nA][0] * inv0, acc[nA][1] * inv0, hv.x, lv.x);
            split_pack(acc[nA][2] * inv1, acc[nA][3] * inv1, hv.y, lv.y);
            split_pack(acc[nB][0] * inv0, acc[nB][1] * inv0, hv.z, lv.z);
            split_pack(acc[nB][2] * inv1, acc[nB][3] * inv1, hv.w, lv.w);
            size_t I = ((size_t)(rowTile * 16 + h * 2 + s2)) * 2048
                     + (warp * 2 + ntp) * 128 + g * 16 + tq * 4;
            *(uint4*)&outHi[I] = hv;
            *(uint4*)&outLo[I] = lv;
        }
    }
}

// ---------------- host ----------------
extern "C" void kernel_launch(void* const* d_in, const int* in_sizes, int n_in,
                              void* d_out, int out_size) {
    const int*   inputs    = (const int*)  d_in[0];
    const float* embed     = (const float*)d_in[1];
    const float* ln1_scale = (const float*)d_in[2];
    const float* ln1_bias  = (const float*)d_in[3];
    const float* wq        = (const float*)d_in[4];
    const float* wk        = (const float*)d_in[5];
    const float* wv        = (const float*)d_in[6];
    const float* wo        = (const float*)d_in[7];
    const float* ln2_scale = (const float*)d_in[8];
    const float* ln2_bias  = (const float*)d_in[9];
    const float* w1        = (const float*)d_in[10];
    const float* b1        = (const float*)d_in[11];
    const float* w2        = (const float*)d_in[12];
    const float* b2        = (const float*)d_in[13];
    const float* lnf_scale = (const float*)d_in[14];
    const float* lnf_bias  = (const float*)d_in[15];
    float* out = (float*)d_out;

    static float *px = nullptr, *pq, *pk, *pv, *pkv, *pz;
    static uint32_t *hAhi, *hAlo, *ndhi, *ndlo, *pthi, *ptlo, *whi, *wlo;
    if (!px) {
        cudaGetSymbolAddress((void**)&px,   g_x);
        cudaGetSymbolAddress((void**)&pq,   g_phiq);
        cudaGetSymbolAddress((void**)&pk,   g_phik);
        cudaGetSymbolAddress((void**)&pv,   g_v);
        cudaGetSymbolAddress((void**)&pkv,  g_kv);
        cudaGetSymbolAddress((void**)&pz,   g_z);
        cudaGetSymbolAddress((void**)&hAhi, g_hAhi);
        cudaGetSymbolAddress((void**)&hAlo, g_hAlo);
        cudaGetSymbolAddress((void**)&ndhi, g_ndhi);
        cudaGetSymbolAddress((void**)&ndlo, g_ndlo);
        cudaGetSymbolAddress((void**)&pthi, g_pthi);
        cudaGetSymbolAddress((void**)&ptlo, g_ptlo);
        cudaGetSymbolAddress((void**)&whi,  g_whi);
        cudaGetSymbolAddress((void**)&wlo,  g_wlo);
        cudaFuncSetAttribute(gemm_tc<6,0>, cudaFuncAttributeMaxDynamicSharedMemorySize, SMEM_BYTES);
        cudaFuncSetAttribute(gemm_tc<5,0>, cudaFuncAttributeMaxDynamicSharedMemorySize, SMEM_BYTES);
        cudaFuncSetAttribute(gemm_tc<3,1>, cudaFuncAttributeMaxDynamicSharedMemorySize, SMEM_BYTES);
        cudaFuncSetAttribute(gemm_tc<4,0>, cudaFuncAttributeMaxDynamicSharedMemorySize, SMEM_BYTES);
        cudaFuncSetAttribute(numden_mma, cudaFuncAttributeMaxDynamicSharedMemorySize, ND_SMEM);
    }

    dim3 gQKV(12, Nrows / 128);
    dim3 gE(4, Nrows / 128);
    dim3 gM(16, Nrows / 128);
    dim3 gKV(Bz * Hz, KV_SPLITS);
    dim3 gND(Bz * Hz, Sz / 128);

    // our launches: 0 split_qkv, 1 zero_all-pre, 2 embed, 3 PROBE numden_mma
    // (ncu -s 5; garbage out, overwritten by layer 0), 4 zero_all, 5 ln1...
    split_qkv<<<dim3(2, 32, 3 * Lz), 256>>>(wq, wk, wv, whi + OFQ, wlo + OFQ);
    zero_all_kernel<<<(Lz * KVSZ + 255) / 256, 256>>>(pkv, pz);
    embed_pe_kernel<<<(Nrows * Ez + 255) / 256, 256>>>(inputs, embed, px);
    numden_mma<<<gND, 256, ND_SMEM>>>(pq, pkv, pz, ndhi, ndlo);   // PROBE
    zero_all_kernel<<<(Lz * KVSZ + 255) / 256, 256>>>(pkv, pz);
    layernorm_split<<<Nrows / 16, 256>>>(px, hAhi, hAlo, ln1_scale, ln1_bias);
    gemm_tc<6,0><<<gQKV, 256, SMEM_BYTES>>>(hAhi, hAlo, whi + OFQ, wlo + OFQ,
                                            nullptr, Ez, 512, nullptr, nullptr, inputs,
                                            nullptr, nullptr, pq, pk, pv);
    split_w<<<dim3(2, 32, Lz), 256>>>(wo, whi + OO, wlo + OO, Ez, Ez, (size_t)Ez*Ez, 131072);
    split_w<<<dim3(8, 32, Lz), 256>>>(w1, whi + O1, wlo + O1, Ez, Mz, (size_t)Ez*Mz, 524288);
    split_w<<<dim3(2, 128, Lz), 256>>>(w2, whi + O2, wlo + O2, Mz, Ez, (size_t)Mz*Ez, 524288);

    for (int l = 0; l < Lz; l++) {
        const uint32_t* fqh = whi + OFQ + (size_t)l * 393216;
        const uint32_t* fql = wlo + OFQ + (size_t)l * 393216;
        const uint32_t* woh = whi + OO + (size_t)l * 131072;
        const uint32_t* wol = wlo + OO + (size_t)l * 131072;
        const uint32_t* w1h = whi + O1 + (size_t)l * 524288;
        const uint32_t* w1l = wlo + O1 + (size_t)l * 524288;
        const uint32_t* w2h = whi + O2 + (size_t)l * 524288;
        const uint32_t* w2l = wlo + O2 + (size_t)l * 524288;
        float* kvL = pkv + (size_t)l * KVSZ;
        float* zL  = pz  + (size_t)l * ZSZ;

        if (l > 0) {
            layernorm_split<<<Nrows / 16, 256>>>(px, hAhi, hAlo,
                                                 ln1_scale + l * Ez, ln1_bias + l * Ez);
            gemm_tc<6,0><<<gQKV, 256, SMEM_BYTES>>>(hAhi, hAlo, fqh, fql,
                                                    nullptr, Ez, 512, nullptr, nullptr, inputs,
                                                    nullptr, nullptr, pq, pk, pv);
        }
        kv_kernel<<<gKV, 256>>>(pk, pv, kvL, zL);
        numden_mma<<<gND, 256, ND_SMEM>>>(pq, kvL, zL, ndhi, ndlo);
        gemm_tc<5,0><<<gE, 256, SMEM_BYTES>>>(ndhi, ndlo, woh, wol, px, Ez, Ez,
                                              nullptr, px, nullptr, nullptr, nullptr,
                                              nullptr, nullptr, nullptr);
        layernorm_split<<<Nrows / 16, 256>>>(px, hAhi, hAlo,
                                             ln2_scale + l * Ez, ln2_bias + l * Ez);
        gemm_tc<3,1><<<gM, 256, SMEM_BYTES>>>(hAhi, hAlo, w1h, w1l, nullptr, Ez, Mz,
                                              b1 + (size_t)l * Mz, nullptr, nullptr,
                                              pthi, ptlo, nullptr, nullptr, nullptr);
        gemm_tc<4,0><<<gE, 256, SMEM_BYTES>>>(pthi, ptlo, w2h, w2l, px, Mz, Ez,
                                              b2 + (size_t)l * Ez, px, nullptr,
                                              nullptr, nullptr, nullptr, nullptr, nullptr);
    }

    layernorm_kernel<<<Nrows, 256>>>(px, out, lnf_scale, lnf_bias);
}

// round 17
// speedup vs baseline: 1.1508x; 1.0068x over previous
#include <cuda_runtime.h>
#include <cuda_bf16.h>
#include <math.h>
#include <stdint.h>

#define Bz 4
#define Sz 4096
#define Ez 512
#define Hz 8
#define Dz 64
#define Mz 2048
#define Lz 6
#define Nrows (Bz*Sz)
#define LN_EPS 1e-6f
#define KEPS 1e-3f
#define KVSZ (Bz*Hz*Dz*Dz)
#define ZSZ  (Bz*Hz*Dz)

// ---------------- device scratch ----------------
__device__ float g_x[Nrows*Ez];
__device__ float g_phiq[Nrows*Ez];
__device__ float g_phik[Nrows*Ez];
__device__ float g_v[Nrows*Ez];
__device__ float g_kv[Lz*KVSZ];
__device__ float g_z[Lz*ZSZ];
__device__ __align__(16) uint32_t g_hAhi[Nrows*256];
__device__ __align__(16) uint32_t g_hAlo[Nrows*256];
__device__ __align__(16) uint32_t g_ndhi[Nrows*256];
__device__ __align__(16) uint32_t g_ndlo[Nrows*256];
__device__ __align__(16) uint32_t g_pthi[Nrows*1024];
__device__ __align__(16) uint32_t g_ptlo[Nrows*1024];
#define OFQ 0
#define OO  2359296
#define O1  3145728
#define O2  6291456
#define WTOT 9437184
__device__ __align__(16) uint32_t g_whi[WTOT];
__device__ __align__(16) uint32_t g_wlo[WTOT];

// ---------------- helpers ----------------
__device__ __forceinline__ void split_pack(float x0, float x1,
                                           uint32_t& hi, uint32_t& lo) {
    __nv_bfloat162 h = __floats2bfloat162_rn(x0, x1);
    float r0 = x0 - __bfloat162float(h.x);
    float r1 = x1 - __bfloat162float(h.y);
    __nv_bfloat162 l = __floats2bfloat162_rn(r0, r1);
    hi = *reinterpret_cast<uint32_t*>(&h);
    lo = *reinterpret_cast<uint32_t*>(&l);
}
__device__ __forceinline__ void mma_bf16(float* c, uint4 a, uint2 b) {
    asm volatile(
        "mma.sync.aligned.m16n8k16.row.col.f32.bf16.bf16.f32 "
        "{%0,%1,%2,%3}, {%4,%5,%6,%7}, {%8,%9}, {%0,%1,%2,%3};"
        : "+f"(c[0]), "+f"(c[1]), "+f"(c[2]), "+f"(c[3])
        : "r"(a.x), "r"(a.y), "r"(a.z), "r"(a.w), "r"(b.x), "r"(b.y));
}
__device__ __forceinline__ float warp_sum(float v) {
    #pragma unroll
    for (int o = 16; o; o >>= 1) v += __shfl_xor_sync(0xffffffffu, v, o);
    return v;
}
__device__ __forceinline__ float gelu_tanh(float x) {
    float x3 = x * x * x;
    return 0.5f * x * (1.f + tanhf(0.7978845608028654f * (x + 0.044715f * x3)));
}
__device__ __forceinline__ void cp16(uint32_t dst, const void* src) {
    asm volatile("cp.async.cg.shared.global [%0], [%1], 16;\n" :: "r"(dst), "l"(src));
}
__device__ __forceinline__ void cp_commit() { asm volatile("cp.async.commit_group;\n"); }
template<int N>
__device__ __forceinline__ void cp_wait() {
    asm volatile("cp.async.wait_group %0;\n" :: "n"(N));
}

// ---------------- fused qkv weight split ----------------
__global__ void split_qkv(const float* __restrict__ wq, const float* __restrict__ wk,
                          const float* __restrict__ wv,
                          uint32_t* __restrict__ hi, uint32_t* __restrict__ lo) {
    int z = blockIdx.z, l = z / 3, m = z % 3;
    const float* Wl = (m == 0 ? wq : m == 1 ? wk : wv) + (size_t)l * Ez * Ez;
    uint32_t* hiL = hi + (size_t)l * 393216 + (size_t)m * 131072;
    uint32_t* loL = lo + (size_t)l * 393216 + (size_t)m * 131072;
    int c = blockIdx.x * 256 + threadIdx.x;
    int kb = blockIdx.y;
    int cb = c >> 7, nb = (c >> 3) & 15, g = c & 7;
    int stage = kb >> 1, kbS = kb & 1;
    uint32_t h8[8], l8[8];
    #pragma unroll
    for (int o = 0; o < 8; o++) {
        int tq = o >> 1, hb = o & 1;
        int k = kb * 16 + 2 * tq + 8 * hb;
        split_pack(Wl[(size_t)k * Ez + c], Wl[(size_t)(k + 1) * Ez + c], h8[o], l8[o]);
    }
    size_t I = ((size_t)(cb * 16 + stage)) * 2048 + (kbS * 16 + nb) * 64 + g * 8;
    *(uint4*)&hiL[I]     = *(uint4*)&h8[0];
    *(uint4*)&hiL[I + 4] = *(uint4*)&h8[4];
    *(uint4*)&loL[I]     = *(uint4*)&l8[0];
    *(uint4*)&loL[I + 4] = *(uint4*)&l8[4];
}

// ---------------- generic weight split ----------------
__global__ void split_w(const float* __restrict__ W,
                        uint32_t* __restrict__ hi, uint32_t* __restrict__ lo,
                        int K, int NC, size_t wStrideL, size_t oStrideL) {
    int l = blockIdx.z;
    const float* Wl = W + (size_t)l * wStrideL;
    uint32_t* hiL = hi + (size_t)l * oStrideL;
    uint32_t* loL = lo + (size_t)l * oStrideL;
    int c = blockIdx.x * 256 + threadIdx.x;
    int kb = blockIdx.y;
    int cb = c >> 7, nb = (c >> 3) & 15, g = c & 7;
    int stage = kb >> 1, kbS = kb & 1;
    uint32_t h8[8], l8[8];
    #pragma unroll
    for (int o = 0; o < 8; o++) {
        int tq = o >> 1, hb = o & 1;
        int k = kb * 16 + 2 * tq + 8 * hb;
        split_pack(Wl[(size_t)k * NC + c], Wl[(size_t)(k + 1) * NC + c], h8[o], l8[o]);
    }
    size_t I = ((size_t)(cb * (K >> 5) + stage)) * 2048 + (kbS * 16 + nb) * 64 + g * 8;
    *(uint4*)&hiL[I]     = *(uint4*)&h8[0];
    *(uint4*)&hiL[I + 4] = *(uint4*)&h8[4];
    *(uint4*)&loL[I]     = *(uint4*)&l8[0];
    *(uint4*)&loL[I + 4] = *(uint4*)&l8[4];
}

// ---------------- embedding + PE ----------------
__global__ void embed_pe_kernel(const int* __restrict__ inp,
                                const float* __restrict__ emb,
                                float* __restrict__ x) {
    int idx = blockIdx.x * blockDim.x + threadIdx.x;
    if (idx >= Nrows * Ez) return;
    int e = idx & (Ez - 1);
    int n = idx >> 9;
    int s = n & (Sz - 1);
    int tok = inp[n];
    int j = (e >> 1) * 2;
    const float c = -9.210340371976184f / (float)Ez;
    float ang = (float)s * expf((float)j * c);
    float pe = (e & 1) ? cosf(ang) : sinf(ang);
    x[idx] = emb[(size_t)tok * Ez + e] + pe;
}

// ---------------- zero all kv/z slices ----------------
__global__ void zero_all_kernel(float* kv, float* z) {
    int i = blockIdx.x * blockDim.x + threadIdx.x;
    if (i < Lz * KVSZ) kv[i] = 0.f;
    if (i < Lz * ZSZ) z[i] = 0.f;
}

// ---------------- final plain layernorm ----------------
__device__ __forceinline__ float block_sum(float val, float* red) {
    __syncthreads();
    int t = threadIdx.x;
    #pragma unroll
    for (int o = 16; o; o >>= 1) val += __shfl_down_sync(0xffffffffu, val, o);
    if ((t & 31) == 0) red[t >> 5] = val;
    __syncthreads();
    if (t < 32) {
        float r = (t < 8) ? red[t] : 0.f;
        #pragma unroll
        for (int o = 4; o; o >>= 1) r += __shfl_down_sync(0xffffffffu, r, o);
        if (t == 0) red[0] = r;
    }
    __syncthreads();
    return red[0];
}
__global__ void layernorm_kernel(const float* __restrict__ in,
                                 float* __restrict__ out,
                                 const float* __restrict__ scale,
                                 const float* __restrict__ bias) {
    __shared__ float red[32];
    int n = blockIdx.x;
    int t = threadIdx.x;
    const float* row = in + (size_t)n * Ez;
    float2 v = *(const float2*)&row[t * 2];
    float mu = block_sum(v.x + v.y, red) * (1.f / Ez);
    float dx = v.x - mu, dy = v.y - mu;
    float var = block_sum(dx * dx + dy * dy, red) * (1.f / Ez);
    float rs = rsqrtf(var + LN_EPS);
    float2 o;
    o.x = dx * rs * scale[t * 2 + 0] + bias[t * 2 + 0];
    o.y = dy * rs * scale[t * 2 + 1] + bias[t * 2 + 1];
    *(float2*)&out[(size_t)n * Ez + t * 2] = o;
}

// ---------------- layernorm -> split-permuted (16 rows/block) ----------------
__global__ void layernorm_split(const float* __restrict__ in,
                                uint32_t* __restrict__ outHi,
                                uint32_t* __restrict__ outLo,
                                const float* __restrict__ scale,
                                const float* __restrict__ bias) {
    __shared__ float nrm[16][516];
    int tid = threadIdx.x;
    int warp = tid >> 5, lane = tid & 31;
    long n0 = (long)blockIdx.x * 16;
    #pragma unroll
    for (int rr = 0; rr < 2; rr++) {
        int r = warp * 2 + rr;
        const float* row = in + (n0 + r) * Ez;
        float4 v[4];
        float s = 0.f;
        #pragma unroll
        for (int q = 0; q < 4; q++) {
            v[q] = *(const float4*)&row[lane * 4 + q * 128];
            s += v[q].x + v[q].y + v[q].z + v[q].w;
        }
        float mu = warp_sum(s) * (1.f / Ez);
        float vr = 0.f;
        #pragma unroll
        for (int q = 0; q < 4; q++) {
            float a = v[q].x - mu, b = v[q].y - mu, c = v[q].z - mu, d = v[q].w - mu;
            vr += a * a + b * b + c * c + d * d;
        }
        float rs = rsqrtf(warp_sum(vr) * (1.f / Ez) + LN_EPS);
        #pragma unroll
        for (int q = 0; q < 4; q++) {
            int c = lane * 4 + q * 128;
            float4 sc = *(const float4*)&scale[c];
            float4 bi = *(const float4*)&bias[c];
            float4 o;
            o.x = (v[q].x - mu) * rs * sc.x + bi.x;
            o.y = (v[q].y - mu) * rs * sc.y + bi.y;
            o.z = (v[q].z - mu) * rs * sc.z + bi.z;
            o.w = (v[q].w - mu) * rs * sc.w + bi.w;
            *(float4*)&nrm[r][c] = o;
        }
    }
    __syncthreads();
    int g = tid & 7, kb = (tid >> 3) & 1, stage = tid >> 4;
    uint32_t hi[16], lo[16];
    #pragma unroll
    for (int o = 0; o < 16; o++) {
        int tq = o >> 2, kbit = (o >> 1) & 1, rbit = o & 1;
        int c = stage * 32 + kb * 16 + 2 * tq + 8 * kbit;
        int rl = g + 8 * rbit;
        split_pack(nrm[rl][c], nrm[rl][c + 1], hi[o], lo[o]);
    }
    size_t I = ((size_t)((blockIdx.x >> 3) * 16 + stage)) * 2048
             + ((blockIdx.x & 7) * 2 + kb) * 128 + g * 16;
    *(uint4*)&outHi[I]      = *(uint4*)&hi[0];
    *(uint4*)&outHi[I + 4]  = *(uint4*)&hi[4];
    *(uint4*)&outHi[I + 8]  = *(uint4*)&hi[8];
    *(uint4*)&outHi[I + 12] = *(uint4*)&hi[12];
    *(uint4*)&outLo[I]      = *(uint4*)&lo[0];
    *(uint4*)&outLo[I + 4]  = *(uint4*)&lo[4];
    *(uint4*)&outLo[I + 8]  = *(uint4*)&lo[8];
    *(uint4*)&outLo[I + 12] = *(uint4*)&lo[12];
}

// ---------------- tensor-core GEMM (R8 config) ----------------
#define SMEM_BYTES 98304
template<int EPI, int OUT>
__global__ void __launch_bounds__(256, 2)
gemm_tc(const uint32_t* __restrict__ Ahi, const uint32_t* __restrict__ Alo,
        const uint32_t* __restrict__ Bhi, const uint32_t* __restrict__ Blo,
        float* __restrict__ C, int K, int NC,
        const float* __restrict__ bias, const float* __restrict__ resid,
        const int* __restrict__ maskTok,
        uint32_t* __restrict__ outHi, uint32_t* __restrict__ outLo,
        float* __restrict__ oq, float* __restrict__ ok, float* __restrict__ ov) {
    extern __shared__ uint32_t sm[];
    const int tid = threadIdx.x;
    const int lane = tid & 31, warp = tid >> 5;
    const int wm = warp & 1, wn = warp >> 1;
    const int g = lane >> 2, tq = lane & 3;
    const int NS = K >> 5;
    const size_t aBase = (size_t)blockIdx.y * NS * 2048;
    const size_t bBase = (size_t)blockIdx.x * NS * 2048;
    const uint32_t smBase = (uint32_t)__cvta_generic_to_shared(sm);

    float acc[4][4][4];
    #pragma unroll
    for (int mt = 0; mt < 4; mt++)
        #pragma unroll
        for (int nt = 0; nt < 4; nt++)
            #pragma unroll
            for (int r = 0; r < 4; r++) acc[mt][nt][r] = 0.f;

    auto issue = [&](int s) {
        uint32_t d = smBase + (s % 3) * 32768 + tid * 16;
        const uint32_t* a1 = Ahi + aBase + (size_t)s * 2048 + tid * 4;
        const uint32_t* a2 = Alo + aBase + (size_t)s * 2048 + tid * 4;
        const uint32_t* b1 = Bhi + bBase + (size_t)s * 2048 + tid * 4;
        const uint32_t* b2 = Blo + bBase + (size_t)s * 2048 + tid * 4;
        cp16(d,          a1); cp16(d + 4096,  a1 + 1024);
        cp16(d + 8192,   a2); cp16(d + 12288, a2 + 1024);
        cp16(d + 16384,  b1); cp16(d + 20480, b1 + 1024);
        cp16(d + 24576,  b2); cp16(d + 28672, b2 + 1024);
    };

    issue(0); cp_commit();
    issue(1); cp_commit();

    for (int s = 0; s < NS; s++) {
        if (s + 1 < NS) cp_wait<1>(); else cp_wait<0>();
        __syncthreads();
        if (s + 2 < NS) { issue(s + 2); cp_commit(); }
        int base = (s % 3) * 8192;
        #pragma unroll
        for (int kb = 0; kb < 2; kb++) {
            uint4 Ah[4], Al[4]; uint2 Bh[4], Bl[4];
            #pragma unroll
            for (int mt = 0; mt < 4; mt++) {
                int blk = base + ((wm * 4 + mt) * 2 + kb) * 128 + lane * 4;
                Ah[mt] = *(uint4*)&sm[blk];
                Al[mt] = *(uint4*)&sm[blk + 2048];
            }
            #pragma unroll
            for (int nt = 0; nt < 4; nt++) {
                int bo = base + 4096 + (kb * 16 + wn * 4 + nt) * 64 + lane * 2;
                Bh[nt] = *(uint2*)&sm[bo];
                Bl[nt] = *(uint2*)&sm[bo + 2048];
            }
            #pragma unroll
            for (int mt = 0; mt < 4; mt++)
                #pragma unroll
                for (int nt = 0; nt < 4; nt++)
                    mma_bf16(acc[mt][nt], Ah[mt], Bh[nt]);
            #pragma unroll
            for (int mt = 0; mt < 4; mt++)
                #pragma unroll
                for (int nt = 0; nt < 4; nt++)
                    mma_bf16(acc[mt][nt], Ah[mt], Bl[nt]);
            #pragma unroll
            for (int mt = 0; mt < 4; mt++)
                #pragma unroll
                for (int nt = 0; nt < 4; nt++)
                    mma_bf16(acc[mt][nt], Al[mt], Bh[nt]);
        }
    }

    const long rowBase = (long)blockIdx.y * 128;
    const int colBase = blockIdx.x * 128;

    if (OUT == 1) {
        #pragma unroll
        for (int mt = 0; mt < 4; mt++) {
            float tv[4][4];
            #pragma unroll
            for (int nt = 0; nt < 4; nt++) {
                int c = colBase + wn * 32 + nt * 8 + 2 * tq;
                float b0 = bias[c], b1 = bias[c + 1];
                tv[nt][0] = gelu_tanh(acc[mt][nt][0] + b0);
                tv[nt][1] = gelu_tanh(acc[mt][nt][1] + b1);
                tv[nt][2] = gelu_tanh(acc[mt][nt][2] + b0);
                tv[nt][3] = gelu_tanh(acc[mt][nt][3] + b1);
            }
            #pragma unroll
            for (int ntp = 0; ntp < 2; ntp++) {
                uint4 hv, lv;
                split_pack(tv[2*ntp][0],   tv[2*ntp][1],   hv.x, lv.x);
                split_pack(tv[2*ntp][2],   tv[2*ntp][3],   hv.y, lv.y);
                split_pack(tv[2*ntp+1][0], tv[2*ntp+1][1], hv.z, lv.z);
                split_pack(tv[2*ntp+1][2], tv[2*ntp+1][3], hv.w, lv.w);
                size_t I = ((size_t)blockIdx.y * (NC >> 5) + blockIdx.x * 4 + wn) * 2048
                         + ((wm * 4 + mt) * 2 + ntp) * 128 + g * 16 + tq * 4;
                *(uint4*)&outHi[I] = hv;
                *(uint4*)&outLo[I] = lv;
            }
        }
        return;
    }

    if (EPI == 6) {
        int mat = colBase >> 9;
        int cc0 = colBase & 511;
        float* dst = (mat == 0) ? oq : (mat == 1) ? ok : ov;
        #pragma unroll
        for (int mt = 0; mt < 4; mt++) {
            long r0 = rowBase + wm * 64 + mt * 16 + g;
            long r1 = r0 + 8;
            float m0 = 1.f, m1 = 1.f;
            if (mat == 1) {
                m0 = (maskTok[r0] > 0) ? 1.f : 0.f;
                m1 = (maskTok[r1] > 0) ? 1.f : 0.f;
            }
            #pragma unroll
            for (int nt = 0; nt < 4; nt++) {
                int c = cc0 + wn * 32 + nt * 8 + 2 * tq;
                float v0 = acc[mt][nt][0], v1 = acc[mt][nt][1];
                float v2 = acc[mt][nt][2], v3 = acc[mt][nt][3];
                if (mat == 0) {
                    v0 = fmaxf(v0, 0.f) + KEPS; v1 = fmaxf(v1, 0.f) + KEPS;
                    v2 = fmaxf(v2, 0.f) + KEPS; v3 = fmaxf(v3, 0.f) + KEPS;
                } else if (mat == 1) {
                    v0 = (fmaxf(v0, 0.f) + KEPS) * m0; v1 = (fmaxf(v1, 0.f) + KEPS) * m0;
                    v2 = (fmaxf(v2, 0.f) + KEPS) * m1; v3 = (fmaxf(v3, 0.f) + KEPS) * m1;
                }
                float2 o0 = {v0, v1}, o1 = {v2, v3};
                *(float2*)&dst[(size_t)r0 * 512 + c] = o0;
                *(float2*)&dst[(size_t)r1 * 512 + c] = o1;
            }
        }
        return;
    }

    #pragma unroll
    for (int mt = 0; mt < 4; mt++) {
        long r0 = rowBase + wm * 64 + mt * 16 + g;
        long r1 = r0 + 8;
        #pragma unroll
        for (int nt = 0; nt < 4; nt++) {
            int c = colBase + wn * 32 + nt * 8 + 2 * tq;
            float v0 = acc[mt][nt][0], v1 = acc[mt][nt][1];
            float v2 = acc[mt][nt][2], v3 = acc[mt][nt][3];
            if (EPI == 4) {
                float b0 = bias[c], b1 = bias[c + 1];
                v0 += b0; v1 += b1; v2 += b0; v3 += b1;
            }
            v0 += resid[(size_t)r0 * NC + c];
            v1 += resid[(size_t)r0 * NC + c + 1];
            v2 += resid[(size_t)r1 * NC + c];
            v3 += resid[(size_t)r1 * NC + c + 1];
            float2 o0 = {v0, v1}, o1 = {v2, v3};
            *(float2*)&C[(size_t)r0 * NC + c] = o0;
            *(float2*)&C[(size_t)r1 * NC + c] = o1;
        }
    }
}

// ---------------- kv = phik^T @ v, z = sum phik ----------------
#define KV_SPLITS 32
__global__ void kv_kernel(const float* __restrict__ phik,
                          const float* __restrict__ v,
                          float* __restrict__ kv, float* __restrict__ z) {
    int bh = blockIdx.x, split = blockIdx.y;
    int b = bh >> 3, h = bh & 7;
    const int CH = Sz / KV_SPLITS;
    int s0 = split * CH;
    __shared__ float ks[32][64];
    __shared__ float vs[32][64];
    int tid = threadIdx.x;
    int tx = tid & 15, ty = tid >> 4;
    float acc[4][4];
    #pragma unroll
    for (int i = 0; i < 4; i++)
        #pragma unroll
        for (int j = 0; j < 4; j++) acc[i][j] = 0.f;
    float zacc[4] = {0.f, 0.f, 0.f, 0.f};
    for (int c = 0; c < CH; c += 32) {
        #pragma unroll
        for (int r = 0; r < 2; r++) {
            int f4 = tid + r * 256;
            int row = f4 >> 4, col = (f4 & 15) * 4;
            size_t base = ((size_t)(b * Sz + s0 + c + row)) * Ez + h * 64 + col;
            *(float4*)&ks[row][col] = *(const float4*)&phik[base];
            *(float4*)&vs[row][col] = *(const float4*)&v[base];
        }
        __syncthreads();
        #pragma unroll
        for (int s = 0; s < 32; s++) {
            float a[4], bb[4];
            #pragma unroll
            for (int i = 0; i < 4; i++) { a[i] = ks[s][ty * 4 + i]; bb[i] = vs[s][tx * 4 + i]; }
            #pragma unroll
            for (int i = 0; i < 4; i++)
                #pragma unroll
                for (int j = 0; j < 4; j++) acc[i][j] = fmaf(a[i], bb[j], acc[i][j]);
            if (tx == 0)
                #pragma unroll
                for (int i = 0; i < 4; i++) zacc[i] += a[i];
        }
        __syncthreads();
    }
    float* kvp = kv + bh * Dz * Dz;
    #pragma unroll
    for (int i = 0; i < 4; i++)
        #pragma unroll
        for (int j = 0; j < 4; j++)
            atomicAdd(&kvp[(ty * 4 + i) * 64 + tx * 4 + j], acc[i][j]);
    if (tx == 0)
        #pragma unroll
        for (int i = 0; i < 4; i++)
            atomicAdd(&z[bh * 64 + ty * 4 + i], zacc[i]);
}

// ---------------- numden via tensor cores (bf16x3) --------------------------
#define ND_SMEM ((12288 + 64 + 256) * 4)
__global__ void __launch_bounds__(256, 4)
numden_mma(const float* __restrict__ phiq, const float* __restrict__ kv,
           const float* __restrict__ z,
           uint32_t* __restrict__ outHi, uint32_t* __restrict__ outLo) {
    extern __shared__ uint32_t nds[];
    uint32_t* Ah = nds;
    uint32_t* Al = nds + 4096;
    uint32_t* Bh = nds + 8192;
    uint32_t* Bl = nds + 10240;
    float* zsm = (float*)(nds + 12288);
    float* den2 = zsm + 64;

    int bh = blockIdx.x, chunk = blockIdx.y;
    int b = bh >> 3, h = bh & 7;
    int tid = threadIdx.x;

    if (tid < 64) zsm[tid] = z[bh * 64 + tid];
    __syncthreads();

    {
        int kb = tid >> 6, c = tid & 63;
        int nb = c >> 3, gg = c & 7;
        const float* kvp = kv + bh * 4096;
        uint32_t h8[8], l8[8];
        #pragma unroll
        for (int o = 0; o < 8; o++) {
            int tqv = o >> 1, hb = o & 1;
            int k = kb * 16 + 2 * tqv + 8 * hb;
            split_pack(kvp[k * 64 + c], kvp[(k + 1) * 64 + c], h8[o], l8[o]);
        }
        int I = kb * 512 + nb * 64 + gg * 8;
        *(uint4*)&Bh[I]     = *(uint4*)&h8[0];
        *(uint4*)&Bh[I + 4] = *(uint4*)&h8[4];
        *(uint4*)&Bl[I]     = *(uint4*)&l8[0];
        *(uint4*)&Bl[I + 4] = *(uint4*)&l8[4];
    }

    {
        int r = tid >> 1, half = tid & 1;
        const float* src = phiq + ((size_t)(b * Sz + chunk * 128 + r)) * Ez
                         + h * 64 + half * 32;
        float dp = 0.f;
        #pragma unroll
        for (int q = 0; q < 8; q++) {
            float4 v4 = *(const float4*)&src[q * 4];
            int cb = half * 32 + q * 4;
            dp = fmaf(v4.x, zsm[cb], fmaf(v4.y, zsm[cb + 1],
                 fmaf(v4.z, zsm[cb + 2], fmaf(v4.w, zsm[cb + 3], dp))));
            uint32_t h0, l0, h1, l1;
            split_pack(v4.x, v4.y, h0, l0);
            split_pack(v4.z, v4.w, h1, l1);
            int I = r * 32 + half * 16 + q * 2;
            Ah[I] = h0; Ah[I + 1] = h1;
            Al[I] = l0; Al[I + 1] = l1;
        }
        den2[r * 2 + half] = dp;
    }
    __syncthreads();

    const int lane = tid & 31, warp = tid >> 5;
    const int g = lane >> 2, tq = lane & 3;
    const int rb = warp * 16;

    float acc[8][4];
    #pragma unroll
    for (int nt = 0; nt < 8; nt++)
        #pragma unroll
        for (int r = 0; r < 4; r++) acc[nt][r] = 0.f;

    #pragma unroll
    for (int kb = 0; kb < 4; kb++) {
        uint4 ah, al;
        ah.x = Ah[(rb + g) * 32 + kb * 8 + tq];
        ah.y = Ah[(rb + g + 8) * 32 + kb * 8 + tq];
        ah.z = Ah[(rb + g) * 32 + kb * 8 + tq + 4];
        ah.w = Ah[(rb + g + 8) * 32 + kb * 8 + tq + 4];
        al.x = Al[(rb + g) * 32 + kb * 8 + tq];
        al.y = Al[(rb + g + 8) * 32 + kb * 8 + tq];
        al.z = Al[(rb + g) * 32 + kb * 8 + tq + 4];
        al.w = Al[(rb + g + 8) * 32 + kb * 8 + tq + 4];
        uint2 bhf[8], blf[8];
        #pragma unroll
        for (int nt = 0; nt < 8; nt++) {
            bhf[nt] = *(uint2*)&Bh[kb * 512 + nt * 64 + lane * 2];
            blf[nt] = *(uint2*)&Bl[kb * 512 + nt * 64 + lane * 2];
        }
        #pragma unroll
        for (int nt = 0; nt < 8; nt++) mma_bf16(acc[nt], ah, bhf[nt]);
        #pragma unroll
        for (int nt = 0; nt < 8; nt++) mma_bf16(acc[nt], ah, blf[nt]);
        #pragma unroll
        for (int nt = 0; nt < 8; nt++) mma_bf16(acc[nt], al, bhf[nt]);
    }

    float inv0 = 1.f / (den2[(rb + g) * 2] + den2[(rb + g) * 2 + 1]);
    float inv1 = 1.f / (den2[(rb + g + 8) * 2] + den2[(rb + g + 8) * 2 + 1]);

    long rowTile = (long)b * (Sz / 128) + chunk;
    #pragma unroll
    for (int s2 = 0; s2 < 2; s2++) {
        #pragma unroll
        for (int ntp = 0; ntp < 2; ntp++) {
            int nA = s2 * 4 + ntp * 2, nB = nA + 1;
            uint4 hv, lv;
            split_pack(acc[nA][0] * inv0, acc[nA][1] * inv0, hv.x, lv.x);
            split_pack(acc[nA][2] * inv1, acc[nA][3] * inv1, hv.y, lv.y);
            split_pack(acc[nB][0] * inv0, acc[nB][1] * inv0, hv.z, lv.z);
            split_pack(acc[nB][2] * inv1, acc[nB][3] * inv1, hv.w, lv.w);
            size_t I = ((size_t)(rowTile * 16 + h * 2 + s2)) * 2048
                     + (warp * 2 + ntp) * 128 + g * 16 + tq * 4;
            *(uint4*)&outHi[I] = hv;
            *(uint4*)&outLo[I] = lv;
        }
    }
}

// ---------------- host ----------------
extern "C" void kernel_launch(void* const* d_in, const int* in_sizes, int n_in,
                              void* d_out, int out_size) {
    const int*   inputs    = (const int*)  d_in[0];
    const float* embed     = (const float*)d_in[1];
    const float* ln1_scale = (const float*)d_in[2];
    const float* ln1_bias  = (const float*)d_in[3];
    const float* wq        = (const float*)d_in[4];
    const float* wk        = (const float*)d_in[5];
    const float* wv        = (const float*)d_in[6];
    const float* wo        = (const float*)d_in[7];
    const float* ln2_scale = (const float*)d_in[8];
    const float* ln2_bias  = (const float*)d_in[9];
    const float* w1        = (const float*)d_in[10];
    const float* b1        = (const float*)d_in[11];
    const float* w2        = (const float*)d_in[12];
    const float* b2        = (const float*)d_in[13];
    const float* lnf_scale = (const float*)d_in[14];
    const float* lnf_bias  = (const float*)d_in[15];
    float* out = (float*)d_out;

    static float *px = nullptr, *pq, *pk, *pv, *pkv, *pz;
    static uint32_t *hAhi, *hAlo, *ndhi, *ndlo, *pthi, *ptlo, *whi, *wlo;
    if (!px) {
        cudaGetSymbolAddress((void**)&px,   g_x);
        cudaGetSymbolAddress((void**)&pq,   g_phiq);
        cudaGetSymbolAddress((void**)&pk,   g_phik);
        cudaGetSymbolAddress((void**)&pv,   g_v);
        cudaGetSymbolAddress((void**)&pkv,  g_kv);
        cudaGetSymbolAddress((void**)&pz,   g_z);
        cudaGetSymbolAddress((void**)&hAhi, g_hAhi);
        cudaGetSymbolAddress((void**)&hAlo, g_hAlo);
        cudaGetSymbolAddress((void**)&ndhi, g_ndhi);
        cudaGetSymbolAddress((void**)&ndlo, g_ndlo);
        cudaGetSymbolAddress((void**)&pthi, g_pthi);
        cudaGetSymbolAddress((void**)&ptlo, g_ptlo);
        cudaGetSymbolAddress((void**)&whi,  g_whi);
        cudaGetSymbolAddress((void**)&wlo,  g_wlo);
        cudaFuncSetAttribute(gemm_tc<6,0>, cudaFuncAttributeMaxDynamicSharedMemorySize, SMEM_BYTES);
        cudaFuncSetAttribute(gemm_tc<5,0>, cudaFuncAttributeMaxDynamicSharedMemorySize, SMEM_BYTES);
        cudaFuncSetAttribute(gemm_tc<3,1>, cudaFuncAttributeMaxDynamicSharedMemorySize, SMEM_BYTES);
        cudaFuncSetAttribute(gemm_tc<4,0>, cudaFuncAttributeMaxDynamicSharedMemorySize, SMEM_BYTES);
        cudaFuncSetAttribute(numden_mma, cudaFuncAttributeMaxDynamicSharedMemorySize, ND_SMEM);
    }

    dim3 gQKV(12, Nrows / 128);
    dim3 gE(4, Nrows / 128);
    dim3 gM(16, Nrows / 128);
    dim3 gKV(Bz * Hz, KV_SPLITS);
    dim3 gND(Bz * Hz, Sz / 128);

    split_qkv<<<dim3(2, 32, 3 * Lz), 256>>>(wq, wk, wv, whi + OFQ, wlo + OFQ);
    zero_all_kernel<<<(Lz * KVSZ + 255) / 256, 256>>>(pkv, pz);
    embed_pe_kernel<<<(Nrows * Ez + 255) / 256, 256>>>(inputs, embed, px);
    layernorm_split<<<Nrows / 16, 256>>>(px, hAhi, hAlo, ln1_scale, ln1_bias);
    gemm_tc<6,0><<<gQKV, 256, SMEM_BYTES>>>(hAhi, hAlo, whi + OFQ, wlo + OFQ,
                                            nullptr, Ez, 512, nullptr, nullptr, inputs,
                                            nullptr, nullptr, pq, pk, pv);
    split_w<<<dim3(2, 32, Lz), 256>>>(wo, whi + OO, wlo + OO, Ez, Ez, (size_t)Ez*Ez, 131072);
    split_w<<<dim3(8, 32, Lz), 256>>>(w1, whi + O1, wlo + O1, Ez, Mz, (size_t)Ez*Mz, 524288);
    split_w<<<dim3(2, 128, Lz), 256>>>(w2, whi + O2, wlo + O2, Mz, Ez, (size_t)Mz*Ez, 524288);

    for (int l = 0; l < Lz; l++) {
        const uint32_t* fqh = whi + OFQ + (size_t)l * 393216;
        const uint32_t* fql = wlo + OFQ + (size_t)l * 393216;
        const uint32_t* woh = whi + OO + (size_t)l * 131072;
        const uint32_t* wol = wlo + OO + (size_t)l * 131072;
        const uint32_t* w1h = whi + O1 + (size_t)l * 524288;
        const uint32_t* w1l = wlo + O1 + (size_t)l * 524288;
        const uint32_t* w2h = whi + O2 + (size_t)l * 524288;
        const uint32_t* w2l = wlo + O2 + (size_t)l * 524288;
        float* kvL = pkv + (size_t)l * KVSZ;
        float* zL  = pz  + (size_t)l * ZSZ;

        if (l > 0) {
            layernorm_split<<<Nrows / 16, 256>>>(px, hAhi, hAlo,
                                                 ln1_scale + l * Ez, ln1_bias + l * Ez);
            gemm_tc<6,0><<<gQKV, 256, SMEM_BYTES>>>(hAhi, hAlo, fqh, fql,
                                                    nullptr, Ez, 512, nullptr, nullptr, inputs,
                                                    nullptr, nullptr, pq, pk, pv);
        }
        kv_kernel<<<gKV, 256>>>(pk, pv, kvL, zL);
        numden_mma<<<gND, 256, ND_SMEM>>>(pq, kvL, zL, ndhi, ndlo);
        gemm_tc<5,0><<<gE, 256, SMEM_BYTES>>>(ndhi, ndlo, woh, wol, px, Ez, Ez,
                                              nullptr, px, nullptr, nullptr, nullptr,
                                              nullptr, nullptr, nullptr);
        layernorm_split<<<Nrows / 16, 256>>>(px, hAhi, hAlo,
                                             ln2_scale + l * Ez, ln2_bias + l * Ez);
        gemm_tc<3,1><<<gM, 256, SMEM_BYTES>>>(hAhi, hAlo, w1h, w1l, nullptr, Ez, Mz,
                                              b1 + (size_t)l * Mz, nullptr, nullptr,
                                              pthi, ptlo, nullptr, nullptr, nullptr);
        gemm_tc<4,0><<<gE, 256, SMEM_BYTES>>>(pthi, ptlo, w2h, w2l, px, Mz, Ez,
                                              b2 + (size_t)l * Ez, px, nullptr,
                                              nullptr, nullptr, nullptr, nullptr, nullptr);
    }

    layernorm_kernel<<<Nrows, 256>>>(px, out, lnf_scale, lnf_bias);
}